// round 7
// baseline (speedup 1.0000x reference)
#include <cuda_runtime.h>
#include <math.h>

#define NFFT   4096
#define NHALF  2048
#define NSPEC  2049
#define CCH    512
#define NPIX   784
#define NB     8
#define SLOTS  18
#define DOUT   8705
#define NTHR   512

#define NTW    2048     // twiddle table entries (all stage indices < 2048)
#define APAD   4224     // 4096 + 4096/32 padding
#define CPAD   2112     // 2048 + 64
#define SWI(i) ((i) + ((i) >> 5))

__device__ float2 g_acc2[NB][NSPEC];
__device__ float2 g_acc3[NB][NSPEC];
__device__ float  g_first[NB][CCH];

// CSR inverse hash map (built once per launch; h_idx is pixel-independent)
__device__ uint2    g_descA[4096];   // .x = order0 (off<<16|cnt), .y = order1
__device__ uint2    g_descC[2048];   // .x = order2 bin 2j, .y = order2 bin 2j+1
__device__ unsigned g_chans[3 * CCH]; // entry: chan | (sbit<<16)

__device__ __forceinline__ float2 cmul(float2 a, float2 b) {
    return make_float2(a.x * b.x - a.y * b.y, a.x * b.y + a.y * b.x);
}

// ---------------- Stockham radix-8 stage (swizzled smem) ----------------
// Twiddles: w1,w2,w4 loaded (indices < 2048), w3,w5,w6,w7 computed.
// NOTW: final stage (p==0) -> all twiddles 1, skipped.
template<bool INV, bool NOTW>
__device__ __forceinline__ void stage8(const float2* __restrict__ src,
                                       float2* __restrict__ dst,
                                       const float2* __restrict__ tw,
                                       int sh, int ls, int eighth,
                                       int tid, int nt)
{
    const float CC = 0.70710678118654752f;
    for (int t = tid; t < eighth; t += nt) {
        int p = t >> ls;
        int q = t & ((1 << ls) - 1);
        float2 x0 = src[SWI(t)];
        float2 x1 = src[SWI(t + eighth)];
        float2 x2 = src[SWI(t + 2 * eighth)];
        float2 x3 = src[SWI(t + 3 * eighth)];
        float2 x4 = src[SWI(t + 4 * eighth)];
        float2 x5 = src[SWI(t + 5 * eighth)];
        float2 x6 = src[SWI(t + 6 * eighth)];
        float2 x7 = src[SWI(t + 7 * eighth)];

        float2 u0 = {x0.x + x4.x, x0.y + x4.y};
        float2 u1 = {x0.x - x4.x, x0.y - x4.y};
        float2 u2 = {x2.x + x6.x, x2.y + x6.y};
        float2 u3 = {x2.x - x6.x, x2.y - x6.y};
        float2 e0 = {u0.x + u2.x, u0.y + u2.y};
        float2 e2 = {u0.x - u2.x, u0.y - u2.y};
        float2 j3 = {-u3.y, u3.x};
        float2 e1, e3;
        if (!INV) { e1 = {u1.x - j3.x, u1.y - j3.y}; e3 = {u1.x + j3.x, u1.y + j3.y}; }
        else      { e1 = {u1.x + j3.x, u1.y + j3.y}; e3 = {u1.x - j3.x, u1.y - j3.y}; }

        float2 v0 = {x1.x + x5.x, x1.y + x5.y};
        float2 v1 = {x1.x - x5.x, x1.y - x5.y};
        float2 v2 = {x3.x + x7.x, x3.y + x7.y};
        float2 v3 = {x3.x - x7.x, x3.y - x7.y};
        float2 o0 = {v0.x + v2.x, v0.y + v2.y};
        float2 o2 = {v0.x - v2.x, v0.y - v2.y};
        float2 k3 = {-v3.y, v3.x};
        float2 o1, o3;
        if (!INV) { o1 = {v1.x - k3.x, v1.y - k3.y}; o3 = {v1.x + k3.x, v1.y + k3.y}; }
        else      { o1 = {v1.x + k3.x, v1.y + k3.y}; o3 = {v1.x - k3.x, v1.y - k3.y}; }

        float2 t1, t2, t3;
        if (!INV) {
            t1 = { CC * (o1.x + o1.y),  CC * (o1.y - o1.x) };
            t2 = { o2.y, -o2.x };
            t3 = { CC * (o3.y - o3.x), -CC * (o3.x + o3.y) };
        } else {
            t1 = { CC * (o1.x - o1.y),  CC * (o1.y + o1.x) };
            t2 = { -o2.y, o2.x };
            t3 = { -CC * (o3.x + o3.y), CC * (o3.x - o3.y) };
        }
        float2 y0 = {e0.x + o0.x, e0.y + o0.y};
        float2 y4 = {e0.x - o0.x, e0.y - o0.y};
        float2 y1 = {e1.x + t1.x, e1.y + t1.y};
        float2 y5 = {e1.x - t1.x, e1.y - t1.y};
        float2 y2 = {e2.x + t2.x, e2.y + t2.y};
        float2 y6 = {e2.x - t2.x, e2.y - t2.y};
        float2 y3 = {e3.x + t3.x, e3.y + t3.y};
        float2 y7 = {e3.x - t3.x, e3.y - t3.y};

        if (!NOTW) {
            float2 w1 = tw[p << sh];                 // idx <= 511
            float2 w2 = tw[(2 * p) << sh];           // idx <= 1022
            float2 w4 = tw[(4 * p) << sh];           // idx <= 2044
            if (INV) { w1.y = -w1.y; w2.y = -w2.y; w4.y = -w4.y; }
            float2 w3 = cmul(w1, w2);
            float2 w5 = cmul(w1, w4);
            float2 w6 = cmul(w2, w4);
            float2 w7 = cmul(w3, w4);
            y1 = cmul(y1, w1); y2 = cmul(y2, w2); y3 = cmul(y3, w3);
            y4 = cmul(y4, w4); y5 = cmul(y5, w5); y6 = cmul(y6, w6);
            y7 = cmul(y7, w7);
        }

        int s = 1 << ls;
        int o = q + (p << (ls + 3));
        dst[SWI(o)]         = y0;
        dst[SWI(o + s)]     = y1;
        dst[SWI(o + 2*s)]   = y2;
        dst[SWI(o + 3*s)]   = y3;
        dst[SWI(o + 4*s)]   = y4;
        dst[SWI(o + 5*s)]   = y5;
        dst[SWI(o + 6*s)]   = y6;
        dst[SWI(o + 7*s)]   = y7;
    }
}

// ---------------- radix-4 tail stage, final position (p==0 -> no twiddles) ---
template<bool INV>
__device__ __forceinline__ void stage4_notw(const float2* __restrict__ src,
                                            float2* __restrict__ dst,
                                            int ls, int quarter,
                                            int tid, int nt)
{
    for (int t = tid; t < quarter; t += nt) {
        int p = t >> ls;
        int q = t & ((1 << ls) - 1);
        float2 a = src[SWI(t)];
        float2 b = src[SWI(t + quarter)];
        float2 c = src[SWI(t + 2 * quarter)];
        float2 d = src[SWI(t + 3 * quarter)];
        float2 apc  = {a.x + c.x, a.y + c.y};
        float2 amc  = {a.x - c.x, a.y - c.y};
        float2 bpd  = {b.x + d.x, b.y + d.y};
        float2 jbmd = {-(b.y - d.y), b.x - d.x};
        float2 y0 = {apc.x + bpd.x, apc.y + bpd.y};
        float2 y2 = {apc.x - bpd.x, apc.y - bpd.y};
        float2 y1, y3;
        if (!INV) { y1 = {amc.x - jbmd.x, amc.y - jbmd.y}; y3 = {amc.x + jbmd.x, amc.y + jbmd.y}; }
        else      { y1 = {amc.x + jbmd.x, amc.y + jbmd.y}; y3 = {amc.x - jbmd.x, amc.y - jbmd.y}; }
        int s = 1 << ls;
        int o = q + (p << (ls + 2));
        dst[SWI(o)]       = y0;
        dst[SWI(o + s)]   = y1;
        dst[SWI(o + 2*s)] = y2;
        dst[SWI(o + 3*s)] = y3;
    }
}

// 4096-pt FFT (finalize path)
template<bool INV>
__device__ void fft4096_r8(float2* A, float2* B, const float2* tw, int tid, int nt)
{
    stage8<INV, false>(A, B, tw, 0, 0, 512, tid, nt); __syncthreads();
    stage8<INV, false>(B, A, tw, 3, 3, 512, tid, nt); __syncthreads();
    stage8<INV, false>(A, B, tw, 6, 6, 512, tid, nt); __syncthreads();
    stage8<INV, true >(B, A, tw, 9, 9, 512, tid, nt); __syncthreads();
}

// Unscaled bin product: returns 4*P2, 8*P3 (constants folded into finalize).
__device__ __forceinline__ void binprod(float2 Zk, float2 Zm, float2 Gk, float2 Gm,
                                        float2 w, float2& P2, float2& P3)
{
    float2 F0 = { Zk.x + Zm.x,  Zk.y - Zm.y };
    float2 F1 = { Zk.y + Zm.y, -(Zk.x - Zm.x) };
    float2 E  = { Gk.x + Gm.x,  Gk.y - Gm.y };
    float2 O  = { Gk.y + Gm.y, -(Gk.x - Gm.x) };
    float2 F2 = { E.x + w.x * O.x - w.y * O.y, E.y + w.x * O.y + w.y * O.x };
    P2 = cmul(F0, F1);
    P3 = cmul(P2, F2);
}

__global__ void zero_kernel()
{
    int i = blockIdx.x * blockDim.x + threadIdx.x;
    int n = NB * NSPEC * 2;
    if (i < n) {
        ((float*)g_acc2)[i] = 0.f;
        ((float*)g_acc3)[i] = 0.f;
    }
}

// Build deterministic CSR inverse of the hash map. One block per order.
__global__ void build_csr(const int* __restrict__ h_idx,
                          const int* __restrict__ s_bits)
{
    __shared__ int hsh[CCH];
    __shared__ int cnt[4096];
    __shared__ int part[CCH];
    __shared__ int offs[4096];

    int order = blockIdx.x;
    int tid   = threadIdx.x;

    hsh[tid] = h_idx[order * CCH + tid];
    for (int j = tid; j < 4096; j += CCH) cnt[j] = 0;
    __syncthreads();
    atomicAdd(&cnt[hsh[tid]], 1);          // counts only (order-independent)
    __syncthreads();

    // exclusive prefix sum over 4096 bins: 8 per thread + block scan
    int base = tid * 8;
    int s = 0;
    #pragma unroll
    for (int j = 0; j < 8; j++) s += cnt[base + j];
    part[tid] = s;
    __syncthreads();
    for (int d = 1; d < CCH; d <<= 1) {
        int add = (tid >= d) ? part[tid - d] : 0;
        __syncthreads();
        part[tid] += add;
        __syncthreads();
    }
    int run = (tid > 0) ? part[tid - 1] : 0;
    #pragma unroll
    for (int j = 0; j < 8; j++) { offs[base + j] = run; run += cnt[base + j]; }
    __syncthreads();

    for (int k = tid; k < 4096; k += CCH) {
        unsigned d = ((unsigned)offs[k] << 16) | (unsigned)cnt[k];
        if (order == 0)      g_descA[k].x = d;
        else if (order == 1) g_descA[k].y = d;
        else { if (k & 1) g_descC[k >> 1].y = d; else g_descC[k >> 1].x = d; }
    }

    // deterministic rank: count same-bin channels with smaller index
    int h = hsh[tid];
    int rank = 0;
    for (int c = 0; c < tid; c++) if (hsh[c] == h) rank++;
    int sb = s_bits[order * CCH + tid];     // 1 -> +1, 0 -> -1
    g_chans[order * CCH + offs[h] + rank] = (unsigned)tid | ((unsigned)sb << 16);
}

__global__ void first_kernel(const float* __restrict__ x)
{
    int b = blockIdx.x;
    int c = threadIdx.x;
    const float* p = x + (size_t)b * NPIX * CCH + c;
    float s = 0.f;
    #pragma unroll 8
    for (int i = 0; i < NPIX; i++) s += p[(size_t)i * CCH];
    g_first[b][c] = s;
}

__device__ __forceinline__ float gather_bin(unsigned d,
                                            const unsigned* __restrict__ ch,
                                            const float* __restrict__ x_sh)
{
    unsigned n = d & 0xffffu;
    unsigned o = d >> 16;
    float v = 0.f;
    for (unsigned i = 0; i < n; i++) {
        unsigned e = ch[o + i];
        float xv = x_sh[e & 0xffffu];
        v += (e & 0x10000u) ? xv : -xv;
    }
    return v;
}

__global__ void __launch_bounds__(NTHR, 1)
poly_sketch_kernel(const float* __restrict__ x)
{
    extern __shared__ float2 smem[];
    float2*   tw    = smem;                         // NTW
    float2*   A     = smem + NTW;                   // APAD
    float2*   B     = A + APAD;                     // APAD
    float2*   Cc    = B + APAD;                     // CPAD
    float2*   D     = Cc + CPAD;                    // CPAD
    uint2*    descA = (uint2*)(D + CPAD);           // 4096
    uint2*    descC = descA + 4096;                 // 2048
    unsigned* chsh  = (unsigned*)(descC + 2048);    // 1536
    float*    x_sh  = (float*)(chsh + 1536);        // 512

    int tid  = threadIdx.x;
    int b    = blockIdx.x / SLOTS;
    int slot = blockIdx.x % SLOTS;

    for (int j = tid; j < NTW; j += NTHR) {
        float sn, cs;
        sincospif(-(float)j * (1.0f / 2048.0f), &sn, &cs);
        tw[j] = make_float2(cs, sn);
    }
    for (int j = tid; j < 4096; j += NTHR) descA[j] = g_descA[j];
    for (int j = tid; j < 2048; j += NTHR) descC[j] = g_descC[j];
    for (int j = tid; j < 1536; j += NTHR) chsh[j]  = g_chans[j];
    __syncthreads();

    float2 a2[5], a3[5];
    #pragma unroll
    for (int i = 0; i < 5; i++) { a2[i] = make_float2(0.f, 0.f); a3[i] = make_float2(0.f, 0.f); }

    for (int pix = slot; pix < NPIX; pix += SLOTS) {
        x_sh[tid] = x[((size_t)(b * NPIX + pix)) * CCH + tid];
        __syncthreads();

        // gather-scatter: every bin written (no atomics, no zero-fill needed)
        #pragma unroll
        for (int it = 0; it < 8; it++) {
            int k = tid + it * 512;
            uint2 d = descA[k];
            float v0 = gather_bin(d.x, chsh, x_sh);           // order 0 -> real
            float v1 = gather_bin(d.y, chsh + CCH, x_sh);     // order 1 -> imag
            A[SWI(k)] = make_float2(v0, v1);
        }
        #pragma unroll
        for (int it = 0; it < 4; it++) {
            int j = tid + it * 512;
            uint2 d = descC[j];
            float v0 = gather_bin(d.x, chsh + 2 * CCH, x_sh); // bin 2j
            float v1 = gather_bin(d.y, chsh + 2 * CCH, x_sh); // bin 2j+1
            Cc[SWI(j)] = make_float2(v0, v1);
        }
        __syncthreads();

        // interleaved FFT phases: 4096-pt (A<->B) + 2048-pt (Cc<->D)
        stage8<false, false>(A, B, tw, 0, 0, 512, tid, NTHR);
        stage8<false, false>(Cc, D, tw, 1, 0, 256, tid, NTHR);
        __syncthreads();
        stage8<false, false>(B, A, tw, 3, 3, 512, tid, NTHR);
        stage8<false, false>(D, Cc, tw, 4, 3, 256, tid, NTHR);
        __syncthreads();
        stage8<false, false>(A, B, tw, 6, 6, 512, tid, NTHR);
        stage8<false, false>(Cc, D, tw, 7, 6, 256, tid, NTHR);
        __syncthreads();
        stage8<false, true >(B, A, tw, 9, 9, 512, tid, NTHR);
        stage4_notw<false>(D, Cc, 9, 512, tid, NTHR);
        __syncthreads();
        // Z (s0+i*s1 spectrum) in A; G (s2 even/odd-packed spectrum) in Cc

        #pragma unroll
        for (int jj = 0; jj < 2; jj++) {
            int k  = tid + jj * 512;
            int km = (NFFT - k) & (NFFT - 1);
            int kb = 2048 - k;
            int jm = (NHALF - k) & (NHALF - 1);
            float2 Zk  = A[SWI(k)];
            float2 Zm  = A[SWI(km)];
            float2 Zk2 = A[SWI(kb)];
            float2 Zm2 = A[SWI(2048 + k)];
            float2 Gk  = Cc[SWI(k)];
            float2 Gm  = Cc[SWI(jm)];
            float2 w   = tw[k];
            float2 P2a, P3a, P2b, P3b;
            binprod(Zk,  Zm,  Gk, Gm, w, P2a, P3a);
            binprod(Zk2, Zm2, Gm, Gk, make_float2(-w.x, w.y), P2b, P3b);
            a2[2*jj].x   += P2a.x; a2[2*jj].y   += P2a.y;
            a3[2*jj].x   += P3a.x; a3[2*jj].y   += P3a.y;
            a2[2*jj+1].x += P2b.x; a2[2*jj+1].y += P2b.y;
            a3[2*jj+1].x += P3b.x; a3[2*jj+1].y += P3b.y;
        }
        if (tid == 0) {                       // self-paired bin 1024
            float2 Zk = A[SWI(1024)], Zm = A[SWI(3072)];
            float2 Gk = Cc[SWI(1024)];
            float2 P2e, P3e;
            binprod(Zk, Zm, Gk, Gk, make_float2(0.f, -1.f), P2e, P3e);
            a2[4].x += P2e.x; a2[4].y += P2e.y;
            a3[4].x += P3e.x; a3[4].y += P3e.y;
        }
    }

    int bins[4] = { tid, 2048 - tid, tid + 512, 1536 - tid };
    #pragma unroll
    for (int i = 0; i < 4; i++) {
        atomicAdd(&g_acc2[b][bins[i]].x, a2[i].x);
        atomicAdd(&g_acc2[b][bins[i]].y, a2[i].y);
        atomicAdd(&g_acc3[b][bins[i]].x, a3[i].x);
        atomicAdd(&g_acc3[b][bins[i]].y, a3[i].y);
    }
    if (tid == 0) {
        atomicAdd(&g_acc2[b][1024].x, a2[4].x);
        atomicAdd(&g_acc2[b][1024].y, a2[4].y);
        atomicAdd(&g_acc3[b][1024].x, a3[4].x);
        atomicAdd(&g_acc3[b][1024].y, a3[4].y);
    }
}

__global__ void __launch_bounds__(NTHR, 1)
finalize_kernel(const float* __restrict__ alpha, float* __restrict__ out)
{
    extern __shared__ float2 smem[];
    float2* tw  = smem;                 // NTW
    float2* A   = smem + NTW;
    float2* B   = A + APAD;
    float*  phi = (float*)(B + APAD);   // 8712 floats
    __shared__ float red[17];

    int tid = threadIdx.x;
    int b   = blockIdx.x;

    for (int j = tid; j < NTW; j += NTHR) {
        float sn, cs;
        sincospif(-(float)j * (1.0f / 2048.0f), &sn, &cs);
        tw[j] = make_float2(cs, sn);
    }
    __syncthreads();

    // accumulators carry 4x (acc2) and 8x (acc3) -> fold 0.25 / 0.125 here
    const float inv_n = 1.0f / ((float)NPIX * (float)NFFT);

    for (int i = tid; i < NFFT; i += NTHR) {
        if (i <= NHALF) A[SWI(i)] = g_acc2[b][i];
        else { float2 v = g_acc2[b][NFFT - i]; A[SWI(i)] = make_float2(v.x, -v.y); }
    }
    __syncthreads();
    fft4096_r8<true>(A, B, tw, tid, NTHR);
    {
        float a2c = alpha[2] * inv_n * 0.25f;
        for (int i = tid; i < NFFT; i += NTHR) phi[513 + i] = A[SWI(i)].x * a2c;
    }
    __syncthreads();

    for (int i = tid; i < NFFT; i += NTHR) {
        if (i <= NHALF) A[SWI(i)] = g_acc3[b][i];
        else { float2 v = g_acc3[b][NFFT - i]; A[SWI(i)] = make_float2(v.x, -v.y); }
    }
    __syncthreads();
    fft4096_r8<true>(A, B, tw, tid, NTHR);
    {
        float a3c = alpha[3] * inv_n * 0.125f;
        for (int i = tid; i < NFFT; i += NTHR) phi[513 + NFFT + i] = A[SWI(i)].x * a3c;
    }

    if (tid == 0) phi[0] = alpha[0];
    phi[1 + tid] = alpha[1] * g_first[b][tid] * (1.0f / (float)NPIX);
    __syncthreads();

    float lsum = 0.f;
    for (int i = tid; i < DOUT; i += NTHR) {
        float v = phi[i];
        float r;
        if (v > 0.f)      r =  sqrtf(v + 1e-12f);
        else if (v < 0.f) r = -sqrtf(-v + 1e-12f);
        else              r = 0.f;
        phi[i] = r;
        lsum += r * r;
    }
    #pragma unroll
    for (int off = 16; off > 0; off >>= 1)
        lsum += __shfl_down_sync(0xffffffffu, lsum, off);
    if ((tid & 31) == 0) red[tid >> 5] = lsum;
    __syncthreads();
    if (tid == 0) {
        float s = 0.f;
        #pragma unroll
        for (int k = 0; k < 16; k++) s += red[k];
        red[16] = 1.0f / sqrtf(s);
    }
    __syncthreads();
    float rn = red[16];
    for (int i = tid; i < DOUT; i += NTHR)
        out[(size_t)b * DOUT + i] = phi[i] * rn;
}

extern "C" void kernel_launch(void* const* d_in, const int* in_sizes, int n_in,
                              void* d_out, int out_size)
{
    const float* x     = (const float*)d_in[0];
    const float* alpha = (const float*)d_in[1];
    const int*   h     = (const int*)d_in[2];
    const int*   sb    = (const int*)d_in[3];
    float*       out   = (float*)d_out;

    const int MAIN_SMEM = (NTW + 2 * APAD + 2 * CPAD) * (int)sizeof(float2)
                        + 4096 * 8 + 2048 * 8 + 1536 * 4 + 512 * 4;       // 175104
    const int FIN_SMEM  = (NTW + 2 * APAD) * (int)sizeof(float2) + 8712 * 4; // 118816

    cudaFuncSetAttribute(poly_sketch_kernel,
                         cudaFuncAttributeMaxDynamicSharedMemorySize, MAIN_SMEM);
    cudaFuncSetAttribute(finalize_kernel,
                         cudaFuncAttributeMaxDynamicSharedMemorySize, FIN_SMEM);

    zero_kernel<<<(NB * NSPEC * 2 + 255) / 256, 256>>>();
    build_csr<<<3, CCH>>>(h, sb);
    first_kernel<<<NB, CCH>>>(x);
    poly_sketch_kernel<<<NB * SLOTS, NTHR, MAIN_SMEM>>>(x);
    finalize_kernel<<<NB, NTHR, FIN_SMEM>>>(alpha, out);
}

// round 8
// speedup vs baseline: 1.8296x; 1.8296x over previous
#include <cuda_runtime.h>
#include <math.h>

#define NFFT   4096
#define NHALF  2048
#define NSPEC  2049
#define CCH    512
#define NPIX   784
#define NB     8
#define SLOTS  18
#define DOUT   8705
#define NTHR   512

#define NTW    2048     // twiddle table entries (all stage indices < 2048)
#define APAD   4224     // 4096 + 4096/32 padding
#define CPAD   2112     // 2048 + 64
#define SWI(i) ((i) + ((i) >> 5))

__device__ float2 g_acc2[NB][NSPEC];
__device__ float2 g_acc3[NB][NSPEC];
__device__ float  g_first[NB][CCH];

// Compact inverse hash map (hash is pixel-invariant; built once per launch).
// g_cbins[o][t]: .x = target FLOAT index (swizzle pre-applied) into A (o=0,1) or
//                     Cc (o=2); .y = chanlist off<<16 | cnt.  cnt==0 -> inactive.
__device__ uint2    g_cbins[3][CCH];
__device__ unsigned g_chans[3 * CCH];   // entry: chan | (sbit<<16), grouped by bin

__device__ __forceinline__ float2 cmul(float2 a, float2 b) {
    return make_float2(a.x * b.x - a.y * b.y, a.x * b.y + a.y * b.x);
}

// ---------------- Stockham radix-8 stage (swizzled smem) ----------------
// Twiddles: w1,w2,w4 loaded (indices < 2048), w3,w5,w6,w7 computed.
// NOTW: final stage (p==0) -> all twiddles 1, skipped.
template<bool INV, bool NOTW>
__device__ __forceinline__ void stage8(const float2* __restrict__ src,
                                       float2* __restrict__ dst,
                                       const float2* __restrict__ tw,
                                       int sh, int ls, int eighth,
                                       int tid, int nt)
{
    const float CC = 0.70710678118654752f;
    for (int t = tid; t < eighth; t += nt) {
        int p = t >> ls;
        int q = t & ((1 << ls) - 1);
        float2 x0 = src[SWI(t)];
        float2 x1 = src[SWI(t + eighth)];
        float2 x2 = src[SWI(t + 2 * eighth)];
        float2 x3 = src[SWI(t + 3 * eighth)];
        float2 x4 = src[SWI(t + 4 * eighth)];
        float2 x5 = src[SWI(t + 5 * eighth)];
        float2 x6 = src[SWI(t + 6 * eighth)];
        float2 x7 = src[SWI(t + 7 * eighth)];

        float2 u0 = {x0.x + x4.x, x0.y + x4.y};
        float2 u1 = {x0.x - x4.x, x0.y - x4.y};
        float2 u2 = {x2.x + x6.x, x2.y + x6.y};
        float2 u3 = {x2.x - x6.x, x2.y - x6.y};
        float2 e0 = {u0.x + u2.x, u0.y + u2.y};
        float2 e2 = {u0.x - u2.x, u0.y - u2.y};
        float2 j3 = {-u3.y, u3.x};
        float2 e1, e3;
        if (!INV) { e1 = {u1.x - j3.x, u1.y - j3.y}; e3 = {u1.x + j3.x, u1.y + j3.y}; }
        else      { e1 = {u1.x + j3.x, u1.y + j3.y}; e3 = {u1.x - j3.x, u1.y - j3.y}; }

        float2 v0 = {x1.x + x5.x, x1.y + x5.y};
        float2 v1 = {x1.x - x5.x, x1.y - x5.y};
        float2 v2 = {x3.x + x7.x, x3.y + x7.y};
        float2 v3 = {x3.x - x7.x, x3.y - x7.y};
        float2 o0 = {v0.x + v2.x, v0.y + v2.y};
        float2 o2 = {v0.x - v2.x, v0.y - v2.y};
        float2 k3 = {-v3.y, v3.x};
        float2 o1, o3;
        if (!INV) { o1 = {v1.x - k3.x, v1.y - k3.y}; o3 = {v1.x + k3.x, v1.y + k3.y}; }
        else      { o1 = {v1.x + k3.x, v1.y + k3.y}; o3 = {v1.x - k3.x, v1.y - k3.y}; }

        float2 t1, t2, t3;
        if (!INV) {
            t1 = { CC * (o1.x + o1.y),  CC * (o1.y - o1.x) };
            t2 = { o2.y, -o2.x };
            t3 = { CC * (o3.y - o3.x), -CC * (o3.x + o3.y) };
        } else {
            t1 = { CC * (o1.x - o1.y),  CC * (o1.y + o1.x) };
            t2 = { -o2.y, o2.x };
            t3 = { -CC * (o3.x + o3.y), CC * (o3.x - o3.y) };
        }
        float2 y0 = {e0.x + o0.x, e0.y + o0.y};
        float2 y4 = {e0.x - o0.x, e0.y - o0.y};
        float2 y1 = {e1.x + t1.x, e1.y + t1.y};
        float2 y5 = {e1.x - t1.x, e1.y - t1.y};
        float2 y2 = {e2.x + t2.x, e2.y + t2.y};
        float2 y6 = {e2.x - t2.x, e2.y - t2.y};
        float2 y3 = {e3.x + t3.x, e3.y + t3.y};
        float2 y7 = {e3.x - t3.x, e3.y - t3.y};

        if (!NOTW) {
            float2 w1 = tw[p << sh];                 // idx <= 511
            float2 w2 = tw[(2 * p) << sh];           // idx <= 1022
            float2 w4 = tw[(4 * p) << sh];           // idx <= 2044
            if (INV) { w1.y = -w1.y; w2.y = -w2.y; w4.y = -w4.y; }
            float2 w3 = cmul(w1, w2);
            float2 w5 = cmul(w1, w4);
            float2 w6 = cmul(w2, w4);
            float2 w7 = cmul(w3, w4);
            y1 = cmul(y1, w1); y2 = cmul(y2, w2); y3 = cmul(y3, w3);
            y4 = cmul(y4, w4); y5 = cmul(y5, w5); y6 = cmul(y6, w6);
            y7 = cmul(y7, w7);
        }

        int s = 1 << ls;
        int o = q + (p << (ls + 3));
        dst[SWI(o)]         = y0;
        dst[SWI(o + s)]     = y1;
        dst[SWI(o + 2*s)]   = y2;
        dst[SWI(o + 3*s)]   = y3;
        dst[SWI(o + 4*s)]   = y4;
        dst[SWI(o + 5*s)]   = y5;
        dst[SWI(o + 6*s)]   = y6;
        dst[SWI(o + 7*s)]   = y7;
    }
}

// ---------------- radix-4 tail stage, final position (p==0 -> no twiddles) ---
template<bool INV>
__device__ __forceinline__ void stage4_notw(const float2* __restrict__ src,
                                            float2* __restrict__ dst,
                                            int ls, int quarter,
                                            int tid, int nt)
{
    for (int t = tid; t < quarter; t += nt) {
        int p = t >> ls;
        int q = t & ((1 << ls) - 1);
        float2 a = src[SWI(t)];
        float2 b = src[SWI(t + quarter)];
        float2 c = src[SWI(t + 2 * quarter)];
        float2 d = src[SWI(t + 3 * quarter)];
        float2 apc  = {a.x + c.x, a.y + c.y};
        float2 amc  = {a.x - c.x, a.y - c.y};
        float2 bpd  = {b.x + d.x, b.y + d.y};
        float2 jbmd = {-(b.y - d.y), b.x - d.x};
        float2 y0 = {apc.x + bpd.x, apc.y + bpd.y};
        float2 y2 = {apc.x - bpd.x, apc.y - bpd.y};
        float2 y1, y3;
        if (!INV) { y1 = {amc.x - jbmd.x, amc.y - jbmd.y}; y3 = {amc.x + jbmd.x, amc.y + jbmd.y}; }
        else      { y1 = {amc.x + jbmd.x, amc.y + jbmd.y}; y3 = {amc.x - jbmd.x, amc.y - jbmd.y}; }
        int s = 1 << ls;
        int o = q + (p << (ls + 2));
        dst[SWI(o)]       = y0;
        dst[SWI(o + s)]   = y1;
        dst[SWI(o + 2*s)] = y2;
        dst[SWI(o + 3*s)] = y3;
    }
}

// 4096-pt FFT (finalize path)
template<bool INV>
__device__ void fft4096_r8(float2* A, float2* B, const float2* tw, int tid, int nt)
{
    stage8<INV, false>(A, B, tw, 0, 0, 512, tid, nt); __syncthreads();
    stage8<INV, false>(B, A, tw, 3, 3, 512, tid, nt); __syncthreads();
    stage8<INV, false>(A, B, tw, 6, 6, 512, tid, nt); __syncthreads();
    stage8<INV, true >(B, A, tw, 9, 9, 512, tid, nt); __syncthreads();
}

// Unscaled bin product: returns 4*P2, 8*P3 (constants folded into finalize).
__device__ __forceinline__ void binprod(float2 Zk, float2 Zm, float2 Gk, float2 Gm,
                                        float2 w, float2& P2, float2& P3)
{
    float2 F0 = { Zk.x + Zm.x,  Zk.y - Zm.y };
    float2 F1 = { Zk.y + Zm.y, -(Zk.x - Zm.x) };
    float2 E  = { Gk.x + Gm.x,  Gk.y - Gm.y };
    float2 O  = { Gk.y + Gm.y, -(Gk.x - Gm.x) };
    float2 F2 = { E.x + w.x * O.x - w.y * O.y, E.y + w.x * O.y + w.y * O.x };
    P2 = cmul(F0, F1);
    P3 = cmul(P2, F2);
}

__global__ void zero_kernel()
{
    int i = blockIdx.x * blockDim.x + threadIdx.x;
    int n = NB * NSPEC * 2;
    if (i < n) {
        ((float*)g_acc2)[i] = 0.f;
        ((float*)g_acc3)[i] = 0.f;
    }
}

// Build deterministic compact inverse hash map. One block per order.
__global__ void build_csr(const int* __restrict__ h_idx,
                          const int* __restrict__ s_bits)
{
    __shared__ int hsh[CCH];
    __shared__ int cnt[4096];
    __shared__ int part[CCH];
    __shared__ int offs[4096];

    int order = blockIdx.x;
    int tid   = threadIdx.x;

    hsh[tid] = h_idx[order * CCH + tid];
    for (int j = tid; j < 4096; j += CCH) cnt[j] = 0;
    __syncthreads();
    atomicAdd(&cnt[hsh[tid]], 1);          // counts only (order-independent)
    __syncthreads();

    // exclusive prefix sum over 4096 bins: 8 per thread + block scan
    int base = tid * 8;
    int s = 0;
    #pragma unroll
    for (int j = 0; j < 8; j++) s += cnt[base + j];
    part[tid] = s;
    __syncthreads();
    for (int d = 1; d < CCH; d <<= 1) {
        int add = (tid >= d) ? part[tid - d] : 0;
        __syncthreads();
        part[tid] += add;
        __syncthreads();
    }
    int run = (tid > 0) ? part[tid - 1] : 0;
    #pragma unroll
    for (int j = 0; j < 8; j++) { offs[base + j] = run; run += cnt[base + j]; }
    __syncthreads();

    // channel list grouped by bin; rank = same-bin channels with smaller index
    int h = hsh[tid];
    int rank = 0;
    for (int c = 0; c < tid; c++) if (hsh[c] == h) rank++;
    int sb = s_bits[order * CCH + tid];     // 1 -> +1, 0 -> -1
    g_chans[order * CCH + offs[h] + rank] = (unsigned)tid | ((unsigned)sb << 16);

    // compact nonempty bins (deterministic order = bin index order)
    __syncthreads();
    int nz = 0;
    #pragma unroll
    for (int j = 0; j < 8; j++) nz += (cnt[base + j] > 0);
    part[tid] = nz;
    __syncthreads();
    for (int d = 1; d < CCH; d <<= 1) {
        int add = (tid >= d) ? part[tid - d] : 0;
        __syncthreads();
        part[tid] += add;
        __syncthreads();
    }
    int pos = (tid > 0) ? part[tid - 1] : 0;
    #pragma unroll
    for (int j = 0; j < 8; j++) {
        int k = base + j;
        if (cnt[k] > 0) {
            unsigned fidx = (order == 2) ? (unsigned)(2 * SWI(k >> 1) + (k & 1))
                                         : (unsigned)(2 * SWI(k) + order);
            g_cbins[order][pos] = make_uint2(fidx,
                                   ((unsigned)offs[k] << 16) | (unsigned)cnt[k]);
            pos++;
        }
    }
    // pad the tail with inactive entries (cnt == 0)
    int total = part[CCH - 1];
    for (int k = total + tid; k < CCH; k += CCH)
        g_cbins[order][k] = make_uint2(0u, 0u);
}

__global__ void first_kernel(const float* __restrict__ x)
{
    int b = blockIdx.x;
    int c = threadIdx.x;
    const float* p = x + (size_t)b * NPIX * CCH + c;
    float s = 0.f;
    #pragma unroll 8
    for (int i = 0; i < NPIX; i++) s += p[(size_t)i * CCH];
    g_first[b][c] = s;
}

__global__ void __launch_bounds__(NTHR, 1)
poly_sketch_kernel(const float* __restrict__ x)
{
    extern __shared__ float2 smem[];
    float2*   tw   = smem;                         // NTW
    float2*   A    = smem + NTW;                   // APAD
    float2*   B    = A + APAD;                     // APAD
    float2*   Cc   = B + APAD;                     // CPAD
    float2*   D    = Cc + CPAD;                    // CPAD
    unsigned* chsh = (unsigned*)(D + CPAD);        // 1536
    float*    x_sh = (float*)(chsh + 1536);        // 512

    int tid  = threadIdx.x;
    int b    = blockIdx.x / SLOTS;
    int slot = blockIdx.x % SLOTS;

    for (int j = tid; j < NTW; j += NTHR) {
        float sn, cs;
        sincospif(-(float)j * (1.0f / 2048.0f), &sn, &cs);
        tw[j] = make_float2(cs, sn);
    }
    for (int j = tid; j < 1536; j += NTHR) chsh[j] = g_chans[j];

    // one compact-bin entry per thread per order, resident in registers
    uint2 e0 = g_cbins[0][tid];
    uint2 e1 = g_cbins[1][tid];
    uint2 e2 = g_cbins[2][tid];
    unsigned f0 = e0.x, o0 = e0.y >> 16, c0 = e0.y & 0xffffu;
    unsigned f1 = e1.x, o1 = (e1.y >> 16) + CCH, c1 = e1.y & 0xffffu;
    unsigned f2 = e2.x, o2 = (e2.y >> 16) + 2 * CCH, c2 = e2.y & 0xffffu;
    __syncthreads();

    float* Af = (float*)A;
    float* Cf = (float*)Cc;
    float4* A4 = (float4*)A;
    float4* C4 = (float4*)Cc;

    float2 a2[5], a3[5];
    #pragma unroll
    for (int i = 0; i < 5; i++) { a2[i] = make_float2(0.f, 0.f); a3[i] = make_float2(0.f, 0.f); }

    for (int pix = slot; pix < NPIX; pix += SLOTS) {
        // zero sketch arrays (float4) + stage x row
        #pragma unroll
        for (int j = 0; j < 4; j++) A4[tid + j * NTHR] = make_float4(0.f, 0.f, 0.f, 0.f);
        if (tid + 2048 < APAD / 2) A4[tid + 2048] = make_float4(0.f, 0.f, 0.f, 0.f);
        #pragma unroll
        for (int j = 0; j < 2; j++) C4[tid + j * NTHR] = make_float4(0.f, 0.f, 0.f, 0.f);
        if (tid + 1024 < CPAD / 2) C4[tid + 1024] = make_float4(0.f, 0.f, 0.f, 0.f);
        x_sh[tid] = x[((size_t)(b * NPIX + pix)) * CCH + tid];
        __syncthreads();

        // compact gather-scatter: one nonempty bin per thread per order
        if (c0) {
            float v = 0.f;
            for (unsigned i = 0; i < c0; i++) {
                unsigned e = chsh[o0 + i];
                float xv = x_sh[e & 0xffffu];
                v += (e & 0x10000u) ? xv : -xv;
            }
            Af[f0] = v;
        }
        if (c1) {
            float v = 0.f;
            for (unsigned i = 0; i < c1; i++) {
                unsigned e = chsh[o1 + i];
                float xv = x_sh[e & 0xffffu];
                v += (e & 0x10000u) ? xv : -xv;
            }
            Af[f1] = v;
        }
        if (c2) {
            float v = 0.f;
            for (unsigned i = 0; i < c2; i++) {
                unsigned e = chsh[o2 + i];
                float xv = x_sh[e & 0xffffu];
                v += (e & 0x10000u) ? xv : -xv;
            }
            Cf[f2] = v;
        }
        __syncthreads();

        // interleaved FFT phases: 4096-pt (A<->B) + 2048-pt (Cc<->D)
        stage8<false, false>(A, B, tw, 0, 0, 512, tid, NTHR);
        stage8<false, false>(Cc, D, tw, 1, 0, 256, tid, NTHR);
        __syncthreads();
        stage8<false, false>(B, A, tw, 3, 3, 512, tid, NTHR);
        stage8<false, false>(D, Cc, tw, 4, 3, 256, tid, NTHR);
        __syncthreads();
        stage8<false, false>(A, B, tw, 6, 6, 512, tid, NTHR);
        stage8<false, false>(Cc, D, tw, 7, 6, 256, tid, NTHR);
        __syncthreads();
        stage8<false, true >(B, A, tw, 9, 9, 512, tid, NTHR);
        stage4_notw<false>(D, Cc, 9, 512, tid, NTHR);
        __syncthreads();
        // Z (s0+i*s1 spectrum) in A; G (s2 even/odd-packed spectrum) in Cc

        #pragma unroll
        for (int jj = 0; jj < 2; jj++) {
            int k  = tid + jj * 512;
            int km = (NFFT - k) & (NFFT - 1);
            int kb = 2048 - k;
            int jm = (NHALF - k) & (NHALF - 1);
            float2 Zk  = A[SWI(k)];
            float2 Zm  = A[SWI(km)];
            float2 Zk2 = A[SWI(kb)];
            float2 Zm2 = A[SWI(2048 + k)];
            float2 Gk  = Cc[SWI(k)];
            float2 Gm  = Cc[SWI(jm)];
            float2 w   = tw[k];
            float2 P2a, P3a, P2b, P3b;
            binprod(Zk,  Zm,  Gk, Gm, w, P2a, P3a);
            binprod(Zk2, Zm2, Gm, Gk, make_float2(-w.x, w.y), P2b, P3b);
            a2[2*jj].x   += P2a.x; a2[2*jj].y   += P2a.y;
            a3[2*jj].x   += P3a.x; a3[2*jj].y   += P3a.y;
            a2[2*jj+1].x += P2b.x; a2[2*jj+1].y += P2b.y;
            a3[2*jj+1].x += P3b.x; a3[2*jj+1].y += P3b.y;
        }
        if (tid == 0) {                       // self-paired bin 1024
            float2 Zk = A[SWI(1024)], Zm = A[SWI(3072)];
            float2 Gk = Cc[SWI(1024)];
            float2 P2e, P3e;
            binprod(Zk, Zm, Gk, Gk, make_float2(0.f, -1.f), P2e, P3e);
            a2[4].x += P2e.x; a2[4].y += P2e.y;
            a3[4].x += P3e.x; a3[4].y += P3e.y;
        }
        __syncthreads();
    }

    int bins[4] = { tid, 2048 - tid, tid + 512, 1536 - tid };
    #pragma unroll
    for (int i = 0; i < 4; i++) {
        atomicAdd(&g_acc2[b][bins[i]].x, a2[i].x);
        atomicAdd(&g_acc2[b][bins[i]].y, a2[i].y);
        atomicAdd(&g_acc3[b][bins[i]].x, a3[i].x);
        atomicAdd(&g_acc3[b][bins[i]].y, a3[i].y);
    }
    if (tid == 0) {
        atomicAdd(&g_acc2[b][1024].x, a2[4].x);
        atomicAdd(&g_acc2[b][1024].y, a2[4].y);
        atomicAdd(&g_acc3[b][1024].x, a3[4].x);
        atomicAdd(&g_acc3[b][1024].y, a3[4].y);
    }
}

__global__ void __launch_bounds__(NTHR, 1)
finalize_kernel(const float* __restrict__ alpha, float* __restrict__ out)
{
    extern __shared__ float2 smem[];
    float2* tw  = smem;                 // NTW
    float2* A   = smem + NTW;
    float2* B   = A + APAD;
    float*  phi = (float*)(B + APAD);   // 8712 floats
    __shared__ float red[17];

    int tid = threadIdx.x;
    int b   = blockIdx.x;

    for (int j = tid; j < NTW; j += NTHR) {
        float sn, cs;
        sincospif(-(float)j * (1.0f / 2048.0f), &sn, &cs);
        tw[j] = make_float2(cs, sn);
    }
    __syncthreads();

    // accumulators carry 4x (acc2) and 8x (acc3) -> fold 0.25 / 0.125 here
    const float inv_n = 1.0f / ((float)NPIX * (float)NFFT);

    for (int i = tid; i < NFFT; i += NTHR) {
        if (i <= NHALF) A[SWI(i)] = g_acc2[b][i];
        else { float2 v = g_acc2[b][NFFT - i]; A[SWI(i)] = make_float2(v.x, -v.y); }
    }
    __syncthreads();
    fft4096_r8<true>(A, B, tw, tid, NTHR);
    {
        float a2c = alpha[2] * inv_n * 0.25f;
        for (int i = tid; i < NFFT; i += NTHR) phi[513 + i] = A[SWI(i)].x * a2c;
    }
    __syncthreads();

    for (int i = tid; i < NFFT; i += NTHR) {
        if (i <= NHALF) A[SWI(i)] = g_acc3[b][i];
        else { float2 v = g_acc3[b][NFFT - i]; A[SWI(i)] = make_float2(v.x, -v.y); }
    }
    __syncthreads();
    fft4096_r8<true>(A, B, tw, tid, NTHR);
    {
        float a3c = alpha[3] * inv_n * 0.125f;
        for (int i = tid; i < NFFT; i += NTHR) phi[513 + NFFT + i] = A[SWI(i)].x * a3c;
    }

    if (tid == 0) phi[0] = alpha[0];
    phi[1 + tid] = alpha[1] * g_first[b][tid] * (1.0f / (float)NPIX);
    __syncthreads();

    float lsum = 0.f;
    for (int i = tid; i < DOUT; i += NTHR) {
        float v = phi[i];
        float r;
        if (v > 0.f)      r =  sqrtf(v + 1e-12f);
        else if (v < 0.f) r = -sqrtf(-v + 1e-12f);
        else              r = 0.f;
        phi[i] = r;
        lsum += r * r;
    }
    #pragma unroll
    for (int off = 16; off > 0; off >>= 1)
        lsum += __shfl_down_sync(0xffffffffu, lsum, off);
    if ((tid & 31) == 0) red[tid >> 5] = lsum;
    __syncthreads();
    if (tid == 0) {
        float s = 0.f;
        #pragma unroll
        for (int k = 0; k < 16; k++) s += red[k];
        red[16] = 1.0f / sqrtf(s);
    }
    __syncthreads();
    float rn = red[16];
    for (int i = tid; i < DOUT; i += NTHR)
        out[(size_t)b * DOUT + i] = phi[i] * rn;
}

extern "C" void kernel_launch(void* const* d_in, const int* in_sizes, int n_in,
                              void* d_out, int out_size)
{
    const float* x     = (const float*)d_in[0];
    const float* alpha = (const float*)d_in[1];
    const int*   h     = (const int*)d_in[2];
    const int*   sb    = (const int*)d_in[3];
    float*       out   = (float*)d_out;

    const int MAIN_SMEM = (NTW + 2 * APAD + 2 * CPAD) * (int)sizeof(float2)
                        + 1536 * 4 + 512 * 4;                              // 125952
    const int FIN_SMEM  = (NTW + 2 * APAD) * (int)sizeof(float2) + 8712 * 4; // 118816

    cudaFuncSetAttribute(poly_sketch_kernel,
                         cudaFuncAttributeMaxDynamicSharedMemorySize, MAIN_SMEM);
    cudaFuncSetAttribute(finalize_kernel,
                         cudaFuncAttributeMaxDynamicSharedMemorySize, FIN_SMEM);

    zero_kernel<<<(NB * NSPEC * 2 + 255) / 256, 256>>>();
    build_csr<<<3, CCH>>>(h, sb);
    first_kernel<<<NB, CCH>>>(x);
    poly_sketch_kernel<<<NB * SLOTS, NTHR, MAIN_SMEM>>>(x);
    finalize_kernel<<<NB, NTHR, FIN_SMEM>>>(alpha, out);
}

// round 9
// speedup vs baseline: 2.3275x; 1.2721x over previous
#include <cuda_runtime.h>
#include <math.h>

#define NFFT   4096
#define NHALF  2048
#define NSPEC  2049
#define CCH    512
#define NPIX   784
#define NB     8
#define SLOTS  18
#define DOUT   8705
#define NTHR   512

#define NTW    2048     // twiddle table entries (all stage indices < 2048)
#define APAD   4224     // 4096 + 4096/32 padding
#define CPAD   2112     // 2048 + 64
#define SWI(i) ((i) + ((i) >> 5))

__device__ float2 g_acc2[NB][NSPEC];
__device__ float2 g_acc3[NB][NSPEC];
__device__ float  g_first[NB][CCH];

typedef unsigned long long u64c;   // packed complex: lo = re, hi = im

__device__ __forceinline__ u64c cadd(u64c a, u64c b) {
    u64c r; asm("add.rn.f32x2 %0,%1,%2;" : "=l"(r) : "l"(a), "l"(b)); return r;
}
__device__ __forceinline__ u64c csub(u64c a, u64c b) {
    u64c r; asm("sub.rn.f32x2 %0,%1,%2;" : "=l"(r) : "l"(a), "l"(b)); return r;
}
__device__ __forceinline__ u64c cscale(u64c a, u64c k) {
    u64c r; asm("mul.rn.f32x2 %0,%1,%2;" : "=l"(r) : "l"(a), "l"(k)); return r;
}
__device__ __forceinline__ u64c cmuli(u64c a) {      // i*a = (-im, re)
    float x, y; asm("mov.b64 {%0,%1},%2;" : "=f"(x), "=f"(y) : "l"(a));
    float ny = -y;
    u64c r; asm("mov.b64 %0,{%1,%2};" : "=l"(r) : "f"(ny), "f"(x)); return r;
}
__device__ __forceinline__ u64c cmulmi(u64c a) {     // -i*a = (im, -re)
    float x, y; asm("mov.b64 {%0,%1},%2;" : "=f"(x), "=f"(y) : "l"(a));
    float nx = -x;
    u64c r; asm("mov.b64 %0,{%1,%2};" : "=l"(r) : "f"(y), "f"(nx)); return r;
}
__device__ __forceinline__ float2 unpk(u64c a) {
    float2 r; asm("mov.b64 {%0,%1},%2;" : "=f"(r.x), "=f"(r.y) : "l"(a)); return r;
}
__device__ __forceinline__ u64c cc2_const() {        // {CC, CC}
    u64c r; float c = 0.70710678118654752f;
    asm("mov.b64 %0,{%1,%1};" : "=l"(r) : "f"(c)); return r;
}

__device__ __forceinline__ float2 cmul(float2 a, float2 b) {
    return make_float2(a.x * b.x - a.y * b.y, a.x * b.y + a.y * b.x);
}

// ---------------- Stockham radix-8 stage (swizzled smem, f32x2 packed) -------
// Twiddles: w1,w2,w4 loaded (indices < 2048), w3,w5,w6,w7 computed (scalar).
// NOTW: final stage (p==0) -> all twiddles 1, skipped, packed stores.
template<bool INV, bool NOTW>
__device__ __forceinline__ void stage8(const float2* __restrict__ src,
                                       float2* __restrict__ dst,
                                       const float2* __restrict__ tw,
                                       int sh, int ls, int eighth,
                                       int tid, int nt)
{
    const u64c CC2 = cc2_const();
    for (int t = tid; t < eighth; t += nt) {
        int p = t >> ls;
        int q = t & ((1 << ls) - 1);
        u64c x0 = *(const u64c*)&src[SWI(t)];
        u64c x1 = *(const u64c*)&src[SWI(t + eighth)];
        u64c x2 = *(const u64c*)&src[SWI(t + 2 * eighth)];
        u64c x3 = *(const u64c*)&src[SWI(t + 3 * eighth)];
        u64c x4 = *(const u64c*)&src[SWI(t + 4 * eighth)];
        u64c x5 = *(const u64c*)&src[SWI(t + 5 * eighth)];
        u64c x6 = *(const u64c*)&src[SWI(t + 6 * eighth)];
        u64c x7 = *(const u64c*)&src[SWI(t + 7 * eighth)];

        u64c u0 = cadd(x0, x4), u1 = csub(x0, x4);
        u64c u2 = cadd(x2, x6), u3 = csub(x2, x6);
        u64c e0 = cadd(u0, u2), e2 = csub(u0, u2);
        u64c j3 = cmuli(u3);
        u64c e1, e3;
        if (!INV) { e1 = csub(u1, j3); e3 = cadd(u1, j3); }
        else      { e1 = cadd(u1, j3); e3 = csub(u1, j3); }

        u64c v0 = cadd(x1, x5), v1 = csub(x1, x5);
        u64c v2 = cadd(x3, x7), v3 = csub(x3, x7);
        u64c o0 = cadd(v0, v2), o2 = csub(v0, v2);
        u64c k3 = cmuli(v3);
        u64c o1, o3;
        if (!INV) { o1 = csub(v1, k3); o3 = cadd(v1, k3); }
        else      { o1 = cadd(v1, k3); o3 = csub(v1, k3); }

        u64c t1, t2, t3;
        if (!INV) {
            t1 = cscale(cadd(o1, cmulmi(o1)), CC2);        // CC*(x+y, y-x)
            t2 = cmulmi(o2);                               // (y, -x)
            t3 = cscale(csub(cmulmi(o3), o3), CC2);        // CC*(y-x, -x-y)
        } else {
            t1 = cscale(cadd(o1, cmuli(o1)), CC2);         // CC*(x-y, y+x)
            t2 = cmuli(o2);                                // (-y, x)
            t3 = cscale(cmuli(cadd(o3, cmuli(o3))), CC2);  // CC*(-(x+y), x-y)
        }
        u64c y0 = cadd(e0, o0), y4 = csub(e0, o0);
        u64c y1 = cadd(e1, t1), y5 = csub(e1, t1);
        u64c y2 = cadd(e2, t2), y6 = csub(e2, t2);
        u64c y3 = cadd(e3, t3), y7 = csub(e3, t3);

        int s = 1 << ls;
        int o = q + (p << (ls + 3));
        if (NOTW) {
            *(u64c*)&dst[SWI(o)]       = y0;
            *(u64c*)&dst[SWI(o + s)]   = y1;
            *(u64c*)&dst[SWI(o + 2*s)] = y2;
            *(u64c*)&dst[SWI(o + 3*s)] = y3;
            *(u64c*)&dst[SWI(o + 4*s)] = y4;
            *(u64c*)&dst[SWI(o + 5*s)] = y5;
            *(u64c*)&dst[SWI(o + 6*s)] = y6;
            *(u64c*)&dst[SWI(o + 7*s)] = y7;
        } else {
            float2 w1 = tw[p << sh];                 // idx <= 511
            float2 w2 = tw[(2 * p) << sh];           // idx <= 1022
            float2 w4 = tw[(4 * p) << sh];           // idx <= 2044
            if (INV) { w1.y = -w1.y; w2.y = -w2.y; w4.y = -w4.y; }
            float2 w3 = cmul(w1, w2);
            float2 w5 = cmul(w1, w4);
            float2 w6 = cmul(w2, w4);
            float2 w7 = cmul(w3, w4);
            dst[SWI(o)]       = unpk(y0);
            dst[SWI(o + s)]   = cmul(unpk(y1), w1);
            dst[SWI(o + 2*s)] = cmul(unpk(y2), w2);
            dst[SWI(o + 3*s)] = cmul(unpk(y3), w3);
            dst[SWI(o + 4*s)] = cmul(unpk(y4), w4);
            dst[SWI(o + 5*s)] = cmul(unpk(y5), w5);
            dst[SWI(o + 6*s)] = cmul(unpk(y6), w6);
            dst[SWI(o + 7*s)] = cmul(unpk(y7), w7);
        }
    }
}

// ---------------- radix-4 tail stage, final position (p==0, packed) ----------
template<bool INV>
__device__ __forceinline__ void stage4_notw(const float2* __restrict__ src,
                                            float2* __restrict__ dst,
                                            int ls, int quarter,
                                            int tid, int nt)
{
    for (int t = tid; t < quarter; t += nt) {
        int p = t >> ls;
        int q = t & ((1 << ls) - 1);
        u64c a = *(const u64c*)&src[SWI(t)];
        u64c b = *(const u64c*)&src[SWI(t + quarter)];
        u64c c = *(const u64c*)&src[SWI(t + 2 * quarter)];
        u64c d = *(const u64c*)&src[SWI(t + 3 * quarter)];
        u64c apc  = cadd(a, c), amc = csub(a, c);
        u64c bpd  = cadd(b, d);
        u64c jbmd = cmuli(csub(b, d));
        u64c y0 = cadd(apc, bpd), y2 = csub(apc, bpd);
        u64c y1, y3;
        if (!INV) { y1 = csub(amc, jbmd); y3 = cadd(amc, jbmd); }
        else      { y1 = cadd(amc, jbmd); y3 = csub(amc, jbmd); }
        int s = 1 << ls;
        int o = q + (p << (ls + 2));
        *(u64c*)&dst[SWI(o)]       = y0;
        *(u64c*)&dst[SWI(o + s)]   = y1;
        *(u64c*)&dst[SWI(o + 2*s)] = y2;
        *(u64c*)&dst[SWI(o + 3*s)] = y3;
    }
}

// 4096-pt FFT (finalize path)
template<bool INV>
__device__ void fft4096_r8(float2* A, float2* B, const float2* tw, int tid, int nt)
{
    stage8<INV, false>(A, B, tw, 0, 0, 512, tid, nt); __syncthreads();
    stage8<INV, false>(B, A, tw, 3, 3, 512, tid, nt); __syncthreads();
    stage8<INV, false>(A, B, tw, 6, 6, 512, tid, nt); __syncthreads();
    stage8<INV, true >(B, A, tw, 9, 9, 512, tid, nt); __syncthreads();
}

// Unscaled bin product: returns 4*P2, 8*P3 (constants folded into finalize).
__device__ __forceinline__ void binprod(float2 Zk, float2 Zm, float2 Gk, float2 Gm,
                                        float2 w, float2& P2, float2& P3)
{
    float2 F0 = { Zk.x + Zm.x,  Zk.y - Zm.y };
    float2 F1 = { Zk.y + Zm.y, -(Zk.x - Zm.x) };
    float2 E  = { Gk.x + Gm.x,  Gk.y - Gm.y };
    float2 O  = { Gk.y + Gm.y, -(Gk.x - Gm.x) };
    float2 F2 = { E.x + w.x * O.x - w.y * O.y, E.y + w.x * O.y + w.y * O.x };
    P2 = cmul(F0, F1);
    P3 = cmul(P2, F2);
}

__global__ void zero_kernel()
{
    int i = blockIdx.x * blockDim.x + threadIdx.x;
    int n = NB * NSPEC * 2;
    if (i < n) {
        ((float*)g_acc2)[i] = 0.f;
        ((float*)g_acc3)[i] = 0.f;
    }
    if (i < NB * CCH) ((float*)g_first)[i] = 0.f;
}

__global__ void __launch_bounds__(NTHR, 1)
poly_sketch_kernel(const float* __restrict__ x,
                   const int* __restrict__ h_idx,
                   const int* __restrict__ s_bits)
{
    extern __shared__ float2 smem[];
    float2* tw = smem;                  // NTW
    float2* A  = smem + NTW;            // APAD
    float2* B  = A + APAD;              // APAD
    float2* Cc = B + APAD;              // CPAD
    float2* D  = Cc + CPAD;             // CPAD

    int tid  = threadIdx.x;
    int b    = blockIdx.x / SLOTS;
    int slot = blockIdx.x % SLOTS;

    for (int j = tid; j < NTW; j += NTHR) {
        float sn, cs;
        sincospif(-(float)j * (1.0f / 2048.0f), &sn, &cs);
        tw[j] = make_float2(cs, sn);
    }
    for (int j = tid; j < APAD; j += NTHR) A[j] = make_float2(0.f, 0.f);
    for (int j = tid; j < CPAD; j += NTHR) Cc[j] = make_float2(0.f, 0.f);

    int   h0 = h_idx[tid],          h1 = h_idx[CCH + tid],        h2 = h_idx[2 * CCH + tid];
    float s0 = (float)(2 * s_bits[tid] - 1);
    float s1 = (float)(2 * s_bits[CCH + tid] - 1);
    float s2 = (float)(2 * s_bits[2 * CCH + tid] - 1);
    int cfa = 2 * SWI(h2 >> 1) + (h2 & 1);
    __syncthreads();

    float2 a2[5], a3[5];
    #pragma unroll
    for (int i = 0; i < 5; i++) { a2[i] = make_float2(0.f, 0.f); a3[i] = make_float2(0.f, 0.f); }
    float xsum = 0.f;

    const float* xrow = x + (size_t)b * NPIX * CCH + tid;
    float xv = xrow[(size_t)slot * CCH];

    for (int pix = slot; pix < NPIX; pix += SLOTS) {
        atomicAdd(&A[SWI(h0)].x, xv * s0);
        atomicAdd(&A[SWI(h1)].y, xv * s1);
        atomicAdd(&((float*)Cc)[cfa], xv * s2);
        xsum += xv;
        __syncthreads();

        // prefetch next pixel's x while the FFT stages run
        int npix = pix + SLOTS;
        float xnext = (npix < NPIX) ? xrow[(size_t)npix * CCH] : 0.f;

        // interleaved FFT phases: 4096-pt (A<->B) + 2048-pt (Cc<->D)
        stage8<false, false>(A, B, tw, 0, 0, 512, tid, NTHR);
        stage8<false, false>(Cc, D, tw, 1, 0, 256, tid, NTHR);
        __syncthreads();
        stage8<false, false>(B, A, tw, 3, 3, 512, tid, NTHR);
        stage8<false, false>(D, Cc, tw, 4, 3, 256, tid, NTHR);
        __syncthreads();
        stage8<false, false>(A, B, tw, 6, 6, 512, tid, NTHR);
        stage8<false, false>(Cc, D, tw, 7, 6, 256, tid, NTHR);
        __syncthreads();
        stage8<false, true >(B, A, tw, 9, 9, 512, tid, NTHR);
        stage4_notw<false>(D, Cc, 9, 512, tid, NTHR);
        __syncthreads();
        // Z (s0+i*s1 spectrum) in A; G (s2 even/odd-packed spectrum) in Cc

        #pragma unroll
        for (int jj = 0; jj < 2; jj++) {
            int k  = tid + jj * 512;
            int km = (NFFT - k) & (NFFT - 1);
            int kb = 2048 - k;
            int jm = (NHALF - k) & (NHALF - 1);
            float2 Zk  = A[SWI(k)];
            float2 Zm  = A[SWI(km)];
            float2 Zk2 = A[SWI(kb)];
            float2 Zm2 = A[SWI(2048 + k)];
            float2 Gk  = Cc[SWI(k)];
            float2 Gm  = Cc[SWI(jm)];
            float2 w   = tw[k];
            float2 P2a, P3a, P2b, P3b;
            binprod(Zk,  Zm,  Gk, Gm, w, P2a, P3a);
            binprod(Zk2, Zm2, Gm, Gk, make_float2(-w.x, w.y), P2b, P3b);
            a2[2*jj].x   += P2a.x; a2[2*jj].y   += P2a.y;
            a3[2*jj].x   += P3a.x; a3[2*jj].y   += P3a.y;
            a2[2*jj+1].x += P2b.x; a2[2*jj+1].y += P2b.y;
            a3[2*jj+1].x += P3b.x; a3[2*jj+1].y += P3b.y;
            float2 z = make_float2(0.f, 0.f);
            A[SWI(k)] = z; A[SWI(km)] = z; A[SWI(kb)] = z; A[SWI(2048 + k)] = z;
            Cc[SWI(k)] = z; Cc[SWI(jm)] = z;
        }
        if (tid == 0) {                       // self-paired bin 1024
            float2 Zk = A[SWI(1024)], Zm = A[SWI(3072)];
            float2 Gk = Cc[SWI(1024)];
            float2 P2e, P3e;
            binprod(Zk, Zm, Gk, Gk, make_float2(0.f, -1.f), P2e, P3e);
            a2[4].x += P2e.x; a2[4].y += P2e.y;
            a3[4].x += P3e.x; a3[4].y += P3e.y;
            float2 z = make_float2(0.f, 0.f);
            A[SWI(1024)] = z; A[SWI(3072)] = z; Cc[SWI(1024)] = z;
        }
        xv = xnext;
        __syncthreads();
    }

    int bins[4] = { tid, 2048 - tid, tid + 512, 1536 - tid };
    #pragma unroll
    for (int i = 0; i < 4; i++) {
        atomicAdd(&g_acc2[b][bins[i]].x, a2[i].x);
        atomicAdd(&g_acc2[b][bins[i]].y, a2[i].y);
        atomicAdd(&g_acc3[b][bins[i]].x, a3[i].x);
        atomicAdd(&g_acc3[b][bins[i]].y, a3[i].y);
    }
    if (tid == 0) {
        atomicAdd(&g_acc2[b][1024].x, a2[4].x);
        atomicAdd(&g_acc2[b][1024].y, a2[4].y);
        atomicAdd(&g_acc3[b][1024].x, a3[4].x);
        atomicAdd(&g_acc3[b][1024].y, a3[4].y);
    }
    atomicAdd(&g_first[b][tid], xsum);
}

__global__ void __launch_bounds__(NTHR, 1)
finalize_kernel(const float* __restrict__ alpha, float* __restrict__ out)
{
    extern __shared__ float2 smem[];
    float2* tw  = smem;                 // NTW
    float2* A   = smem + NTW;
    float2* B   = A + APAD;
    float*  phi = (float*)(B + APAD);   // 8712 floats
    __shared__ float red[17];

    int tid = threadIdx.x;
    int b   = blockIdx.x;

    for (int j = tid; j < NTW; j += NTHR) {
        float sn, cs;
        sincospif(-(float)j * (1.0f / 2048.0f), &sn, &cs);
        tw[j] = make_float2(cs, sn);
    }
    __syncthreads();

    // accumulators carry 4x (acc2) and 8x (acc3) -> fold 0.25 / 0.125 here
    const float inv_n = 1.0f / ((float)NPIX * (float)NFFT);

    for (int i = tid; i < NFFT; i += NTHR) {
        if (i <= NHALF) A[SWI(i)] = g_acc2[b][i];
        else { float2 v = g_acc2[b][NFFT - i]; A[SWI(i)] = make_float2(v.x, -v.y); }
    }
    __syncthreads();
    fft4096_r8<true>(A, B, tw, tid, NTHR);
    {
        float a2c = alpha[2] * inv_n * 0.25f;
        for (int i = tid; i < NFFT; i += NTHR) phi[513 + i] = A[SWI(i)].x * a2c;
    }
    __syncthreads();

    for (int i = tid; i < NFFT; i += NTHR) {
        if (i <= NHALF) A[SWI(i)] = g_acc3[b][i];
        else { float2 v = g_acc3[b][NFFT - i]; A[SWI(i)] = make_float2(v.x, -v.y); }
    }
    __syncthreads();
    fft4096_r8<true>(A, B, tw, tid, NTHR);
    {
        float a3c = alpha[3] * inv_n * 0.125f;
        for (int i = tid; i < NFFT; i += NTHR) phi[513 + NFFT + i] = A[SWI(i)].x * a3c;
    }

    if (tid == 0) phi[0] = alpha[0];
    phi[1 + tid] = alpha[1] * g_first[b][tid] * (1.0f / (float)NPIX);
    __syncthreads();

    float lsum = 0.f;
    for (int i = tid; i < DOUT; i += NTHR) {
        float v = phi[i];
        float r;
        if (v > 0.f)      r =  sqrtf(v + 1e-12f);
        else if (v < 0.f) r = -sqrtf(-v + 1e-12f);
        else              r = 0.f;
        phi[i] = r;
        lsum += r * r;
    }
    #pragma unroll
    for (int off = 16; off > 0; off >>= 1)
        lsum += __shfl_down_sync(0xffffffffu, lsum, off);
    if ((tid & 31) == 0) red[tid >> 5] = lsum;
    __syncthreads();
    if (tid == 0) {
        float s = 0.f;
        #pragma unroll
        for (int k = 0; k < 16; k++) s += red[k];
        red[16] = 1.0f / sqrtf(s);
    }
    __syncthreads();
    float rn = red[16];
    for (int i = tid; i < DOUT; i += NTHR)
        out[(size_t)b * DOUT + i] = phi[i] * rn;
}

extern "C" void kernel_launch(void* const* d_in, const int* in_sizes, int n_in,
                              void* d_out, int out_size)
{
    const float* x     = (const float*)d_in[0];
    const float* alpha = (const float*)d_in[1];
    const int*   h     = (const int*)d_in[2];
    const int*   sb    = (const int*)d_in[3];
    float*       out   = (float*)d_out;

    const int MAIN_SMEM = (NTW + 2 * APAD + 2 * CPAD) * (int)sizeof(float2); // 117760
    const int FIN_SMEM  = (NTW + 2 * APAD) * (int)sizeof(float2) + 8712 * 4; // 118816

    cudaFuncSetAttribute(poly_sketch_kernel,
                         cudaFuncAttributeMaxDynamicSharedMemorySize, MAIN_SMEM);
    cudaFuncSetAttribute(finalize_kernel,
                         cudaFuncAttributeMaxDynamicSharedMemorySize, FIN_SMEM);

    zero_kernel<<<(NB * NSPEC * 2 + 255) / 256, 256>>>();
    poly_sketch_kernel<<<NB * SLOTS, NTHR, MAIN_SMEM>>>(x, h, sb);
    finalize_kernel<<<NB, NTHR, FIN_SMEM>>>(alpha, out);
}

// round 10
// speedup vs baseline: 2.3782x; 1.0218x over previous
#include <cuda_runtime.h>
#include <math.h>

#define NFFT   4096
#define NHALF  2048
#define NSPEC  2049
#define CCH    512
#define NPIX   784
#define NB     8
#define SLOTS  18
#define DOUT   8705
#define NTHR   512

#define NTW    2048     // twiddle table entries (all stage indices < 2048)
#define APAD   4224     // 4096 + 4096/32 padding
#define CPAD   2112     // 2048 + 64
#define SWI(i) ((i) + ((i) >> 5))

__device__ float2 g_acc2[NB][NSPEC];
__device__ float2 g_acc3[NB][NSPEC];
__device__ float  g_first[NB][CCH];

typedef unsigned long long u64c;   // packed complex: lo = re, hi = im

__device__ __forceinline__ u64c cadd(u64c a, u64c b) {
    u64c r; asm("add.rn.f32x2 %0,%1,%2;" : "=l"(r) : "l"(a), "l"(b)); return r;
}
__device__ __forceinline__ u64c csub(u64c a, u64c b) {
    u64c r; asm("sub.rn.f32x2 %0,%1,%2;" : "=l"(r) : "l"(a), "l"(b)); return r;
}
__device__ __forceinline__ u64c cscale(u64c a, u64c k) {
    u64c r; asm("mul.rn.f32x2 %0,%1,%2;" : "=l"(r) : "l"(a), "l"(k)); return r;
}
__device__ __forceinline__ u64c cmuli(u64c a) {      // i*a = (-im, re)
    float x, y; asm("mov.b64 {%0,%1},%2;" : "=f"(x), "=f"(y) : "l"(a));
    float ny = -y;
    u64c r; asm("mov.b64 %0,{%1,%2};" : "=l"(r) : "f"(ny), "f"(x)); return r;
}
__device__ __forceinline__ u64c cmulmi(u64c a) {     // -i*a = (im, -re)
    float x, y; asm("mov.b64 {%0,%1},%2;" : "=f"(x), "=f"(y) : "l"(a));
    float nx = -x;
    u64c r; asm("mov.b64 %0,{%1,%2};" : "=l"(r) : "f"(y), "f"(nx)); return r;
}
__device__ __forceinline__ float2 unpk(u64c a) {
    float2 r; asm("mov.b64 {%0,%1},%2;" : "=f"(r.x), "=f"(r.y) : "l"(a)); return r;
}
__device__ __forceinline__ u64c cc2_const() {        // {CC, CC}
    u64c r; float c = 0.70710678118654752f;
    asm("mov.b64 %0,{%1,%1};" : "=l"(r) : "f"(c)); return r;
}

__device__ __forceinline__ float2 cmul(float2 a, float2 b) {
    return make_float2(a.x * b.x - a.y * b.y, a.x * b.y + a.y * b.x);
}

// ---------------- forward radix-8 butterfly core (packed) --------------------
__device__ __forceinline__ void bf8_fwd(const float2* __restrict__ src,
                                        int t, int eighth, u64c* __restrict__ y)
{
    const u64c CC2 = cc2_const();
    u64c x0 = *(const u64c*)&src[SWI(t)];
    u64c x1 = *(const u64c*)&src[SWI(t + eighth)];
    u64c x2 = *(const u64c*)&src[SWI(t + 2 * eighth)];
    u64c x3 = *(const u64c*)&src[SWI(t + 3 * eighth)];
    u64c x4 = *(const u64c*)&src[SWI(t + 4 * eighth)];
    u64c x5 = *(const u64c*)&src[SWI(t + 5 * eighth)];
    u64c x6 = *(const u64c*)&src[SWI(t + 6 * eighth)];
    u64c x7 = *(const u64c*)&src[SWI(t + 7 * eighth)];

    u64c u0 = cadd(x0, x4), u1 = csub(x0, x4);
    u64c u2 = cadd(x2, x6), u3 = csub(x2, x6);
    u64c e0 = cadd(u0, u2), e2 = csub(u0, u2);
    u64c j3 = cmuli(u3);
    u64c e1 = csub(u1, j3), e3 = cadd(u1, j3);

    u64c v0 = cadd(x1, x5), v1 = csub(x1, x5);
    u64c v2 = cadd(x3, x7), v3 = csub(x3, x7);
    u64c o0 = cadd(v0, v2), o2 = csub(v0, v2);
    u64c k3 = cmuli(v3);
    u64c o1 = csub(v1, k3), o3 = cadd(v1, k3);

    u64c t1 = cscale(cadd(o1, cmulmi(o1)), CC2);
    u64c t2 = cmulmi(o2);
    u64c t3 = cscale(csub(cmulmi(o3), o3), CC2);

    y[0] = cadd(e0, o0); y[4] = csub(e0, o0);
    y[1] = cadd(e1, t1); y[5] = csub(e1, t1);
    y[2] = cadd(e2, t2); y[6] = csub(e2, t2);
    y[3] = cadd(e3, t3); y[7] = csub(e3, t3);
}

__device__ __forceinline__ void store8_tw(float2* __restrict__ dst, int o, int s,
                                          const u64c* __restrict__ y,
                                          float2 w1, float2 w2, float2 w3, float2 w4,
                                          float2 w5, float2 w6, float2 w7)
{
    dst[SWI(o)]       = unpk(y[0]);
    dst[SWI(o + s)]   = cmul(unpk(y[1]), w1);
    dst[SWI(o + 2*s)] = cmul(unpk(y[2]), w2);
    dst[SWI(o + 3*s)] = cmul(unpk(y[3]), w3);
    dst[SWI(o + 4*s)] = cmul(unpk(y[4]), w4);
    dst[SWI(o + 5*s)] = cmul(unpk(y[5]), w5);
    dst[SWI(o + 6*s)] = cmul(unpk(y[6]), w6);
    dst[SWI(o + 7*s)] = cmul(unpk(y[7]), w7);
}

__device__ __forceinline__ void store8_raw(float2* __restrict__ dst, int o, int s,
                                           const u64c* __restrict__ y)
{
    *(u64c*)&dst[SWI(o)]       = y[0];
    *(u64c*)&dst[SWI(o + s)]   = y[1];
    *(u64c*)&dst[SWI(o + 2*s)] = y[2];
    *(u64c*)&dst[SWI(o + 3*s)] = y[3];
    *(u64c*)&dst[SWI(o + 4*s)] = y[4];
    *(u64c*)&dst[SWI(o + 5*s)] = y[5];
    *(u64c*)&dst[SWI(o + 6*s)] = y[6];
    *(u64c*)&dst[SWI(o + 7*s)] = y[7];
}

// Dual 4096-FFT stage: thread t does butterfly t of BOTH pixels, sharing twiddles.
template<bool NOTW>
__device__ __forceinline__ void stageA_dual(const float2* s1, float2* d1,
                                            const float2* s2, float2* d2,
                                            const float2* __restrict__ tw,
                                            int sh, int ls, int tid)
{
    int p = tid >> ls;
    int q = tid & ((1 << ls) - 1);
    int s = 1 << ls;
    int o = q + (p << (ls + 3));
    u64c y[8], z[8];
    bf8_fwd(s1, tid, 512, y);
    bf8_fwd(s2, tid, 512, z);
    if (NOTW) {
        store8_raw(d1, o, s, y);
        store8_raw(d2, o, s, z);
    } else {
        float2 w1 = tw[p << sh];
        float2 w2 = tw[(2 * p) << sh];
        float2 w4 = tw[(4 * p) << sh];
        float2 w3 = cmul(w1, w2);
        float2 w5 = cmul(w1, w4);
        float2 w6 = cmul(w2, w4);
        float2 w7 = cmul(w3, w4);
        store8_tw(d1, o, s, y, w1, w2, w3, w4, w5, w6, w7);
        store8_tw(d2, o, s, z, w1, w2, w3, w4, w5, w6, w7);
    }
}

// Single 2048-FFT radix-8 stage (eighth = 256), explicit butterfly index t.
__device__ __forceinline__ void stageC8(const float2* src, float2* dst,
                                        const float2* __restrict__ tw,
                                        int sh, int ls, int t)
{
    int p = t >> ls;
    int q = t & ((1 << ls) - 1);
    int s = 1 << ls;
    int o = q + (p << (ls + 3));
    u64c y[8];
    bf8_fwd(src, t, 256, y);
    float2 w1 = tw[p << sh];
    float2 w2 = tw[(2 * p) << sh];
    float2 w4 = tw[(4 * p) << sh];
    float2 w3 = cmul(w1, w2);
    float2 w5 = cmul(w1, w4);
    float2 w6 = cmul(w2, w4);
    float2 w7 = cmul(w3, w4);
    store8_tw(dst, o, s, y, w1, w2, w3, w4, w5, w6, w7);
}

// Final radix-4 stage of the 2048 FFT (p-region twiddle-free), both pixels.
__device__ __forceinline__ void stage4_dual(const float2* s1, float2* d1,
                                            const float2* s2, float2* d2,
                                            int ls, int tid)
{
    int p = tid >> ls;
    int q = tid & ((1 << ls) - 1);
    int s = 1 << ls;
    int o = q + (p << (ls + 2));
    #pragma unroll
    for (int which = 0; which < 2; which++) {
        const float2* src = which ? s2 : s1;
        float2* dst = which ? d2 : d1;
        u64c a = *(const u64c*)&src[SWI(tid)];
        u64c b = *(const u64c*)&src[SWI(tid + 512)];
        u64c c = *(const u64c*)&src[SWI(tid + 1024)];
        u64c d = *(const u64c*)&src[SWI(tid + 1536)];
        u64c apc  = cadd(a, c), amc = csub(a, c);
        u64c bpd  = cadd(b, d);
        u64c jbmd = cmuli(csub(b, d));
        u64c y0 = cadd(apc, bpd), y2 = csub(apc, bpd);
        u64c y1 = csub(amc, jbmd), y3 = cadd(amc, jbmd);
        *(u64c*)&dst[SWI(o)]       = y0;
        *(u64c*)&dst[SWI(o + s)]   = y1;
        *(u64c*)&dst[SWI(o + 2*s)] = y2;
        *(u64c*)&dst[SWI(o + 3*s)] = y3;
    }
}

// ---------------- generic stage8 (fwd/inv) for the finalize kernel -----------
template<bool INV, bool NOTW>
__device__ __forceinline__ void stage8(const float2* __restrict__ src,
                                       float2* __restrict__ dst,
                                       const float2* __restrict__ tw,
                                       int sh, int ls, int eighth,
                                       int tid, int nt)
{
    const u64c CC2 = cc2_const();
    for (int t = tid; t < eighth; t += nt) {
        int p = t >> ls;
        int q = t & ((1 << ls) - 1);
        u64c x0 = *(const u64c*)&src[SWI(t)];
        u64c x1 = *(const u64c*)&src[SWI(t + eighth)];
        u64c x2 = *(const u64c*)&src[SWI(t + 2 * eighth)];
        u64c x3 = *(const u64c*)&src[SWI(t + 3 * eighth)];
        u64c x4 = *(const u64c*)&src[SWI(t + 4 * eighth)];
        u64c x5 = *(const u64c*)&src[SWI(t + 5 * eighth)];
        u64c x6 = *(const u64c*)&src[SWI(t + 6 * eighth)];
        u64c x7 = *(const u64c*)&src[SWI(t + 7 * eighth)];

        u64c u0 = cadd(x0, x4), u1 = csub(x0, x4);
        u64c u2 = cadd(x2, x6), u3 = csub(x2, x6);
        u64c e0 = cadd(u0, u2), e2 = csub(u0, u2);
        u64c j3 = cmuli(u3);
        u64c e1, e3;
        if (!INV) { e1 = csub(u1, j3); e3 = cadd(u1, j3); }
        else      { e1 = cadd(u1, j3); e3 = csub(u1, j3); }

        u64c v0 = cadd(x1, x5), v1 = csub(x1, x5);
        u64c v2 = cadd(x3, x7), v3 = csub(x3, x7);
        u64c o0 = cadd(v0, v2), o2 = csub(v0, v2);
        u64c k3 = cmuli(v3);
        u64c o1, o3;
        if (!INV) { o1 = csub(v1, k3); o3 = cadd(v1, k3); }
        else      { o1 = cadd(v1, k3); o3 = csub(v1, k3); }

        u64c t1, t2, t3;
        if (!INV) {
            t1 = cscale(cadd(o1, cmulmi(o1)), CC2);
            t2 = cmulmi(o2);
            t3 = cscale(csub(cmulmi(o3), o3), CC2);
        } else {
            t1 = cscale(cadd(o1, cmuli(o1)), CC2);
            t2 = cmuli(o2);
            t3 = cscale(cmuli(cadd(o3, cmuli(o3))), CC2);
        }
        u64c y0 = cadd(e0, o0), y4 = csub(e0, o0);
        u64c y1 = cadd(e1, t1), y5 = csub(e1, t1);
        u64c y2 = cadd(e2, t2), y6 = csub(e2, t2);
        u64c y3 = cadd(e3, t3), y7 = csub(e3, t3);

        int s = 1 << ls;
        int o = q + (p << (ls + 3));
        if (NOTW) {
            *(u64c*)&dst[SWI(o)]       = y0;
            *(u64c*)&dst[SWI(o + s)]   = y1;
            *(u64c*)&dst[SWI(o + 2*s)] = y2;
            *(u64c*)&dst[SWI(o + 3*s)] = y3;
            *(u64c*)&dst[SWI(o + 4*s)] = y4;
            *(u64c*)&dst[SWI(o + 5*s)] = y5;
            *(u64c*)&dst[SWI(o + 6*s)] = y6;
            *(u64c*)&dst[SWI(o + 7*s)] = y7;
        } else {
            float2 w1 = tw[p << sh];
            float2 w2 = tw[(2 * p) << sh];
            float2 w4 = tw[(4 * p) << sh];
            if (INV) { w1.y = -w1.y; w2.y = -w2.y; w4.y = -w4.y; }
            float2 w3 = cmul(w1, w2);
            float2 w5 = cmul(w1, w4);
            float2 w6 = cmul(w2, w4);
            float2 w7 = cmul(w3, w4);
            dst[SWI(o)]       = unpk(y0);
            dst[SWI(o + s)]   = cmul(unpk(y1), w1);
            dst[SWI(o + 2*s)] = cmul(unpk(y2), w2);
            dst[SWI(o + 3*s)] = cmul(unpk(y3), w3);
            dst[SWI(o + 4*s)] = cmul(unpk(y4), w4);
            dst[SWI(o + 5*s)] = cmul(unpk(y5), w5);
            dst[SWI(o + 6*s)] = cmul(unpk(y6), w6);
            dst[SWI(o + 7*s)] = cmul(unpk(y7), w7);
        }
    }
}

template<bool INV>
__device__ void fft4096_r8(float2* A, float2* B, const float2* tw, int tid, int nt)
{
    stage8<INV, false>(A, B, tw, 0, 0, 512, tid, nt); __syncthreads();
    stage8<INV, false>(B, A, tw, 3, 3, 512, tid, nt); __syncthreads();
    stage8<INV, false>(A, B, tw, 6, 6, 512, tid, nt); __syncthreads();
    stage8<INV, true >(B, A, tw, 9, 9, 512, tid, nt); __syncthreads();
}

// Unscaled bin product: returns 4*P2, 8*P3 (constants folded into finalize).
__device__ __forceinline__ void binprod(float2 Zk, float2 Zm, float2 Gk, float2 Gm,
                                        float2 w, float2& P2, float2& P3)
{
    float2 F0 = { Zk.x + Zm.x,  Zk.y - Zm.y };
    float2 F1 = { Zk.y + Zm.y, -(Zk.x - Zm.x) };
    float2 E  = { Gk.x + Gm.x,  Gk.y - Gm.y };
    float2 O  = { Gk.y + Gm.y, -(Gk.x - Gm.x) };
    float2 F2 = { E.x + w.x * O.x - w.y * O.y, E.y + w.x * O.y + w.y * O.x };
    P2 = cmul(F0, F1);
    P3 = cmul(P2, F2);
}

// Epilogue for one pixel: unpack spectra, accumulate products, zero A/Cc slots.
__device__ __forceinline__ void epilogue(float2* A, float2* Cc,
                                         const float2* __restrict__ tw, int tid,
                                         float2* a2, float2* a3)
{
    #pragma unroll
    for (int jj = 0; jj < 2; jj++) {
        int k  = tid + jj * 512;
        int km = (NFFT - k) & (NFFT - 1);
        int kb = 2048 - k;
        int jm = (NHALF - k) & (NHALF - 1);
        float2 Zk  = A[SWI(k)];
        float2 Zm  = A[SWI(km)];
        float2 Zk2 = A[SWI(kb)];
        float2 Zm2 = A[SWI(2048 + k)];
        float2 Gk  = Cc[SWI(k)];
        float2 Gm  = Cc[SWI(jm)];
        float2 w   = tw[k];
        float2 P2a, P3a, P2b, P3b;
        binprod(Zk,  Zm,  Gk, Gm, w, P2a, P3a);
        binprod(Zk2, Zm2, Gm, Gk, make_float2(-w.x, w.y), P2b, P3b);
        a2[2*jj].x   += P2a.x; a2[2*jj].y   += P2a.y;
        a3[2*jj].x   += P3a.x; a3[2*jj].y   += P3a.y;
        a2[2*jj+1].x += P2b.x; a2[2*jj+1].y += P2b.y;
        a3[2*jj+1].x += P3b.x; a3[2*jj+1].y += P3b.y;
        float2 z = make_float2(0.f, 0.f);
        A[SWI(k)] = z; A[SWI(km)] = z; A[SWI(kb)] = z; A[SWI(2048 + k)] = z;
        Cc[SWI(k)] = z; Cc[SWI(jm)] = z;
    }
    if (tid == 0) {                       // self-paired bin 1024
        float2 Zk = A[SWI(1024)], Zm = A[SWI(3072)];
        float2 Gk = Cc[SWI(1024)];
        float2 P2e, P3e;
        binprod(Zk, Zm, Gk, Gk, make_float2(0.f, -1.f), P2e, P3e);
        a2[4].x += P2e.x; a2[4].y += P2e.y;
        a3[4].x += P3e.x; a3[4].y += P3e.y;
        float2 z = make_float2(0.f, 0.f);
        A[SWI(1024)] = z; A[SWI(3072)] = z; Cc[SWI(1024)] = z;
    }
}

__global__ void zero_kernel()
{
    int i = blockIdx.x * blockDim.x + threadIdx.x;
    int n = NB * NSPEC * 2;
    if (i < n) {
        ((float*)g_acc2)[i] = 0.f;
        ((float*)g_acc3)[i] = 0.f;
    }
    if (i < NB * CCH) ((float*)g_first)[i] = 0.f;
}

__global__ void __launch_bounds__(NTHR, 1)
poly_sketch_kernel(const float* __restrict__ x,
                   const int* __restrict__ h_idx,
                   const int* __restrict__ s_bits)
{
    extern __shared__ float2 smem[];
    float2* tw = smem;                  // NTW
    float2* A1 = smem + NTW;            // APAD
    float2* B1 = A1 + APAD;
    float2* A2 = B1 + APAD;
    float2* B2 = A2 + APAD;
    float2* C1 = B2 + APAD;             // CPAD
    float2* D1 = C1 + CPAD;
    float2* C2 = D1 + CPAD;
    float2* D2 = C2 + CPAD;

    int tid  = threadIdx.x;
    int b    = blockIdx.x / SLOTS;
    int slot = blockIdx.x % SLOTS;

    for (int j = tid; j < NTW; j += NTHR) {
        float sn, cs;
        sincospif(-(float)j * (1.0f / 2048.0f), &sn, &cs);
        tw[j] = make_float2(cs, sn);
    }
    for (int j = tid; j < APAD; j += NTHR) {
        A1[j] = make_float2(0.f, 0.f);
        A2[j] = make_float2(0.f, 0.f);
    }
    for (int j = tid; j < CPAD; j += NTHR) {
        C1[j] = make_float2(0.f, 0.f);
        C2[j] = make_float2(0.f, 0.f);
    }

    int   h0 = h_idx[tid],          h1 = h_idx[CCH + tid],        h2 = h_idx[2 * CCH + tid];
    float s0 = (float)(2 * s_bits[tid] - 1);
    float s1 = (float)(2 * s_bits[CCH + tid] - 1);
    float s2 = (float)(2 * s_bits[2 * CCH + tid] - 1);
    int cfa = 2 * SWI(h2 >> 1) + (h2 & 1);
    __syncthreads();

    float2 a2[5], a3[5];
    #pragma unroll
    for (int i = 0; i < 5; i++) { a2[i] = make_float2(0.f, 0.f); a3[i] = make_float2(0.f, 0.f); }
    float xsum = 0.f;

    const float* xrow = x + (size_t)b * NPIX * CCH + tid;
    float xv1 = xrow[(size_t)slot * CCH];
    float xv2 = (slot + SLOTS < NPIX) ? xrow[(size_t)(slot + SLOTS) * CCH] : 0.f;

    for (int pix = slot; pix < NPIX; pix += 2 * SLOTS) {
        atomicAdd(&A1[SWI(h0)].x, xv1 * s0);
        atomicAdd(&A1[SWI(h1)].y, xv1 * s1);
        atomicAdd(&((float*)C1)[cfa], xv1 * s2);
        atomicAdd(&A2[SWI(h0)].x, xv2 * s0);
        atomicAdd(&A2[SWI(h1)].y, xv2 * s1);
        atomicAdd(&((float*)C2)[cfa], xv2 * s2);
        xsum += xv1 + xv2;
        __syncthreads();

        // prefetch next pixel pair
        int n1 = pix + 2 * SLOTS, n2 = pix + 3 * SLOTS;
        float xn1 = (n1 < NPIX) ? xrow[(size_t)n1 * CCH] : 0.f;
        float xn2 = (n2 < NPIX) ? xrow[(size_t)n2 * CCH] : 0.f;

        // phase 1
        stageA_dual<false>(A1, B1, A2, B2, tw, 0, 0, tid);
        if (tid < 256) stageC8(C1, D1, tw, 1, 0, tid);
        else           stageC8(C2, D2, tw, 1, 0, tid - 256);
        __syncthreads();
        // phase 2
        stageA_dual<false>(B1, A1, B2, A2, tw, 3, 3, tid);
        if (tid < 256) stageC8(D1, C1, tw, 4, 3, tid);
        else           stageC8(D2, C2, tw, 4, 3, tid - 256);
        __syncthreads();
        // phase 3
        stageA_dual<false>(A1, B1, A2, B2, tw, 6, 6, tid);
        if (tid < 256) stageC8(C1, D1, tw, 7, 6, tid);
        else           stageC8(C2, D2, tw, 7, 6, tid - 256);
        __syncthreads();
        // phase 4 (final: twiddle-free)
        stageA_dual<true>(B1, A1, B2, A2, tw, 9, 9, tid);
        stage4_dual(D1, C1, D2, C2, 9, tid);
        __syncthreads();

        epilogue(A1, C1, tw, tid, a2, a3);
        epilogue(A2, C2, tw, tid, a2, a3);

        xv1 = xn1;
        xv2 = xn2;
        __syncthreads();
    }

    int bins[4] = { tid, 2048 - tid, tid + 512, 1536 - tid };
    #pragma unroll
    for (int i = 0; i < 4; i++) {
        atomicAdd(&g_acc2[b][bins[i]].x, a2[i].x);
        atomicAdd(&g_acc2[b][bins[i]].y, a2[i].y);
        atomicAdd(&g_acc3[b][bins[i]].x, a3[i].x);
        atomicAdd(&g_acc3[b][bins[i]].y, a3[i].y);
    }
    if (tid == 0) {
        atomicAdd(&g_acc2[b][1024].x, a2[4].x);
        atomicAdd(&g_acc2[b][1024].y, a2[4].y);
        atomicAdd(&g_acc3[b][1024].x, a3[4].x);
        atomicAdd(&g_acc3[b][1024].y, a3[4].y);
    }
    atomicAdd(&g_first[b][tid], xsum);
}

__global__ void __launch_bounds__(NTHR, 1)
finalize_kernel(const float* __restrict__ alpha, float* __restrict__ out)
{
    extern __shared__ float2 smem[];
    float2* tw  = smem;                 // NTW
    float2* A   = smem + NTW;
    float2* B   = A + APAD;
    float*  phi = (float*)(B + APAD);   // 8712 floats
    __shared__ float red[17];

    int tid = threadIdx.x;
    int b   = blockIdx.x;

    for (int j = tid; j < NTW; j += NTHR) {
        float sn, cs;
        sincospif(-(float)j * (1.0f / 2048.0f), &sn, &cs);
        tw[j] = make_float2(cs, sn);
    }
    __syncthreads();

    // accumulators carry 4x (acc2) and 8x (acc3) -> fold 0.25 / 0.125 here
    const float inv_n = 1.0f / ((float)NPIX * (float)NFFT);

    for (int i = tid; i < NFFT; i += NTHR) {
        if (i <= NHALF) A[SWI(i)] = g_acc2[b][i];
        else { float2 v = g_acc2[b][NFFT - i]; A[SWI(i)] = make_float2(v.x, -v.y); }
    }
    __syncthreads();
    fft4096_r8<true>(A, B, tw, tid, NTHR);
    {
        float a2c = alpha[2] * inv_n * 0.25f;
        for (int i = tid; i < NFFT; i += NTHR) phi[513 + i] = A[SWI(i)].x * a2c;
    }
    __syncthreads();

    for (int i = tid; i < NFFT; i += NTHR) {
        if (i <= NHALF) A[SWI(i)] = g_acc3[b][i];
        else { float2 v = g_acc3[b][NFFT - i]; A[SWI(i)] = make_float2(v.x, -v.y); }
    }
    __syncthreads();
    fft4096_r8<true>(A, B, tw, tid, NTHR);
    {
        float a3c = alpha[3] * inv_n * 0.125f;
        for (int i = tid; i < NFFT; i += NTHR) phi[513 + NFFT + i] = A[SWI(i)].x * a3c;
    }

    if (tid == 0) phi[0] = alpha[0];
    phi[1 + tid] = alpha[1] * g_first[b][tid] * (1.0f / (float)NPIX);
    __syncthreads();

    float lsum = 0.f;
    for (int i = tid; i < DOUT; i += NTHR) {
        float v = phi[i];
        float r;
        if (v > 0.f)      r =  sqrtf(v + 1e-12f);
        else if (v < 0.f) r = -sqrtf(-v + 1e-12f);
        else              r = 0.f;
        phi[i] = r;
        lsum += r * r;
    }
    #pragma unroll
    for (int off = 16; off > 0; off >>= 1)
        lsum += __shfl_down_sync(0xffffffffu, lsum, off);
    if ((tid & 31) == 0) red[tid >> 5] = lsum;
    __syncthreads();
    if (tid == 0) {
        float s = 0.f;
        #pragma unroll
        for (int k = 0; k < 16; k++) s += red[k];
        red[16] = 1.0f / sqrtf(s);
    }
    __syncthreads();
    float rn = red[16];
    for (int i = tid; i < DOUT; i += NTHR)
        out[(size_t)b * DOUT + i] = phi[i] * rn;
}

extern "C" void kernel_launch(void* const* d_in, const int* in_sizes, int n_in,
                              void* d_out, int out_size)
{
    const float* x     = (const float*)d_in[0];
    const float* alpha = (const float*)d_in[1];
    const int*   h     = (const int*)d_in[2];
    const int*   sb    = (const int*)d_in[3];
    float*       out   = (float*)d_out;

    const int MAIN_SMEM = (NTW + 4 * APAD + 4 * CPAD) * (int)sizeof(float2); // 219136
    const int FIN_SMEM  = (NTW + 2 * APAD) * (int)sizeof(float2) + 8712 * 4; // 118816

    cudaFuncSetAttribute(poly_sketch_kernel,
                         cudaFuncAttributeMaxDynamicSharedMemorySize, MAIN_SMEM);
    cudaFuncSetAttribute(finalize_kernel,
                         cudaFuncAttributeMaxDynamicSharedMemorySize, FIN_SMEM);

    zero_kernel<<<(NB * NSPEC * 2 + 255) / 256, 256>>>();
    poly_sketch_kernel<<<NB * SLOTS, NTHR, MAIN_SMEM>>>(x, h, sb);
    finalize_kernel<<<NB, NTHR, FIN_SMEM>>>(alpha, out);
}

// round 11
// speedup vs baseline: 2.5953x; 1.0913x over previous
#include <cuda_runtime.h>
#include <math.h>

#define NFFT   4096
#define NHALF  2048
#define NSPEC  2049
#define CCH    512
#define NPIX   784
#define NB     8
#define SLOTS  18
#define DOUT   8705
#define NTHR   512

#define NTW    2048     // twiddle table entries (all stage indices < 2048)
#define APAD   4224     // 4096 + 4096/32 padding
#define CPAD   2112     // 2048 + 64
#define SWI(i) ((i) + ((i) >> 5))

__device__ float2 g_acc2[NB][NSPEC];
__device__ float2 g_acc3[NB][NSPEC];
__device__ float  g_first[NB][CCH];

typedef unsigned long long u64c;   // packed complex: lo = re, hi = im

__device__ __forceinline__ u64c cadd(u64c a, u64c b) {
    u64c r; asm("add.rn.f32x2 %0,%1,%2;" : "=l"(r) : "l"(a), "l"(b)); return r;
}
__device__ __forceinline__ u64c csub(u64c a, u64c b) {
    u64c r; asm("sub.rn.f32x2 %0,%1,%2;" : "=l"(r) : "l"(a), "l"(b)); return r;
}
__device__ __forceinline__ u64c cscale(u64c a, u64c k) {
    u64c r; asm("mul.rn.f32x2 %0,%1,%2;" : "=l"(r) : "l"(a), "l"(k)); return r;
}
__device__ __forceinline__ u64c cmuli(u64c a) {      // i*a = (-im, re)
    float x, y; asm("mov.b64 {%0,%1},%2;" : "=f"(x), "=f"(y) : "l"(a));
    float ny = -y;
    u64c r; asm("mov.b64 %0,{%1,%2};" : "=l"(r) : "f"(ny), "f"(x)); return r;
}
__device__ __forceinline__ u64c cmulmi(u64c a) {     // -i*a = (im, -re)
    float x, y; asm("mov.b64 {%0,%1},%2;" : "=f"(x), "=f"(y) : "l"(a));
    float nx = -x;
    u64c r; asm("mov.b64 %0,{%1,%2};" : "=l"(r) : "f"(y), "f"(nx)); return r;
}
__device__ __forceinline__ float2 unpk(u64c a) {
    float2 r; asm("mov.b64 {%0,%1},%2;" : "=f"(r.x), "=f"(r.y) : "l"(a)); return r;
}
__device__ __forceinline__ u64c pk2(float x, float y) {
    u64c r; asm("mov.b64 %0,{%1,%2};" : "=l"(r) : "f"(x), "f"(y)); return r;
}
__device__ __forceinline__ u64c cc2_const() {        // {CC, CC}
    u64c r; float c = 0.70710678118654752f;
    asm("mov.b64 %0,{%1,%1};" : "=l"(r) : "f"(c)); return r;
}

__device__ __forceinline__ float2 cmul(float2 a, float2 b) {
    return make_float2(a.x * b.x - a.y * b.y, a.x * b.y + a.y * b.x);
}

// z * (wr + i*wi), constant twiddle
__device__ __forceinline__ u64c cmulc(u64c z, float wr, float wi) {
    float2 a = unpk(z);
    return pk2(a.x * wr - a.y * wi, a.x * wi + a.y * wr);
}
__device__ __forceinline__ u64c w8m1(u64c z, u64c CC2) {  // z * w8^1 = (CC,-CC)
    return cscale(cadd(z, cmulmi(z)), CC2);
}
__device__ __forceinline__ u64c w8m3(u64c z, u64c CC2) {  // z * w8^3 = (-CC,-CC)
    return cscale(csub(cmulmi(z), z), CC2);
}

// ---------------- forward radix-8 butterfly core (packed) --------------------
__device__ __forceinline__ void bf8_fwd(const float2* __restrict__ src,
                                        int t, int eighth, u64c* __restrict__ y)
{
    const u64c CC2 = cc2_const();
    u64c x0 = *(const u64c*)&src[SWI(t)];
    u64c x1 = *(const u64c*)&src[SWI(t + eighth)];
    u64c x2 = *(const u64c*)&src[SWI(t + 2 * eighth)];
    u64c x3 = *(const u64c*)&src[SWI(t + 3 * eighth)];
    u64c x4 = *(const u64c*)&src[SWI(t + 4 * eighth)];
    u64c x5 = *(const u64c*)&src[SWI(t + 5 * eighth)];
    u64c x6 = *(const u64c*)&src[SWI(t + 6 * eighth)];
    u64c x7 = *(const u64c*)&src[SWI(t + 7 * eighth)];

    u64c u0 = cadd(x0, x4), u1 = csub(x0, x4);
    u64c u2 = cadd(x2, x6), u3 = csub(x2, x6);
    u64c e0 = cadd(u0, u2), e2 = csub(u0, u2);
    u64c j3 = cmuli(u3);
    u64c e1 = csub(u1, j3), e3 = cadd(u1, j3);

    u64c v0 = cadd(x1, x5), v1 = csub(x1, x5);
    u64c v2 = cadd(x3, x7), v3 = csub(x3, x7);
    u64c o0 = cadd(v0, v2), o2 = csub(v0, v2);
    u64c k3 = cmuli(v3);
    u64c o1 = csub(v1, k3), o3 = cadd(v1, k3);

    u64c t1 = w8m1(o1, CC2);
    u64c t2 = cmulmi(o2);
    u64c t3 = w8m3(o3, CC2);

    y[0] = cadd(e0, o0); y[4] = csub(e0, o0);
    y[1] = cadd(e1, t1); y[5] = csub(e1, t1);
    y[2] = cadd(e2, t2); y[6] = csub(e2, t2);
    y[3] = cadd(e3, t3); y[7] = csub(e3, t3);
}

__device__ __forceinline__ void store8_raw(float2* __restrict__ dst, int o, int s,
                                           const u64c* __restrict__ y)
{
    *(u64c*)&dst[SWI(o)]       = y[0];
    *(u64c*)&dst[SWI(o + s)]   = y[1];
    *(u64c*)&dst[SWI(o + 2*s)] = y[2];
    *(u64c*)&dst[SWI(o + 3*s)] = y[3];
    *(u64c*)&dst[SWI(o + 4*s)] = y[4];
    *(u64c*)&dst[SWI(o + 5*s)] = y[5];
    *(u64c*)&dst[SWI(o + 6*s)] = y[6];
    *(u64c*)&dst[SWI(o + 7*s)] = y[7];
}

// ---------------- forward Stockham radix-16 stage (one butterfly) ------------
// DFT16 = radix-4 (over m) -> w16^{ja} -> radix-4 (over j); X[a+4b].
// Stage twiddle w_n^{m p}: load W1,W2,W4,W8 (max idx 2040 < NTW), build rest.
template<bool NOTW>
__device__ __forceinline__ void stage16(const float2* __restrict__ src,
                                        float2* __restrict__ dst,
                                        const float2* __restrict__ tw,
                                        int sh, int ls, int t, int sixteenth)
{
    const u64c CC2 = cc2_const();
    const float c1 = 0.92387953251128674f, s1 = 0.38268343236508977f;
    u64c u[4][4];
    #pragma unroll
    for (int j = 0; j < 4; j++) {
        u64c a = *(const u64c*)&src[SWI(t + j * sixteenth)];
        u64c b = *(const u64c*)&src[SWI(t + (j + 4) * sixteenth)];
        u64c c = *(const u64c*)&src[SWI(t + (j + 8) * sixteenth)];
        u64c d = *(const u64c*)&src[SWI(t + (j + 12) * sixteenth)];
        u64c apc = cadd(a, c), amc = csub(a, c);
        u64c bpd = cadd(b, d);
        u64c jb  = cmuli(csub(b, d));
        u[j][0] = cadd(apc, bpd);
        u[j][1] = csub(amc, jb);
        u[j][2] = csub(apc, bpd);
        u[j][3] = cadd(amc, jb);
    }
    // t_j[a] = u_j[a] * w16^{j*a}
    u[1][1] = cmulc(u[1][1],  c1, -s1);   // w16^1
    u[1][2] = w8m1(u[1][2], CC2);         // w16^2
    u[1][3] = cmulc(u[1][3],  s1, -c1);   // w16^3
    u[2][1] = w8m1(u[2][1], CC2);         // w16^2
    u[2][2] = cmulmi(u[2][2]);            // w16^4
    u[2][3] = w8m3(u[2][3], CC2);         // w16^6
    u[3][1] = cmulc(u[3][1],  s1, -c1);   // w16^3
    u[3][2] = w8m3(u[3][2], CC2);         // w16^6
    u[3][3] = cmulc(u[3][3], -c1,  s1);   // w16^9

    u64c y[16];
    #pragma unroll
    for (int a = 0; a < 4; a++) {
        u64c p0 = u[0][a], p1 = u[1][a], p2 = u[2][a], p3 = u[3][a];
        u64c q0 = cadd(p0, p2), q1 = csub(p0, p2);
        u64c q2 = cadd(p1, p3);
        u64c jq = cmuli(csub(p1, p3));
        y[a]      = cadd(q0, q2);
        y[a + 4]  = csub(q1, jq);
        y[a + 8]  = csub(q0, q2);
        y[a + 12] = cadd(q1, jq);
    }

    int p = t >> ls;
    int q = t & ((1 << ls) - 1);
    int s = 1 << ls;
    int o = q + (p << (ls + 4));
    if (NOTW) {
        #pragma unroll
        for (int m = 0; m < 16; m++)
            *(u64c*)&dst[SWI(o + m * s)] = y[m];
    } else {
        float2 W1 = tw[p << sh];
        float2 W2 = tw[(2 * p) << sh];
        float2 W4 = tw[(4 * p) << sh];
        float2 W8 = tw[(8 * p) << sh];
        float2 W3  = cmul(W1, W2), W5  = cmul(W1, W4), W6  = cmul(W2, W4), W7  = cmul(W3, W4);
        float2 W9  = cmul(W1, W8), W10 = cmul(W2, W8), W11 = cmul(W3, W8), W12 = cmul(W4, W8);
        float2 W13 = cmul(W5, W8), W14 = cmul(W6, W8), W15 = cmul(W7, W8);
        dst[SWI(o)]         = unpk(y[0]);
        dst[SWI(o + s)]     = cmul(unpk(y[1]),  W1);
        dst[SWI(o + 2*s)]   = cmul(unpk(y[2]),  W2);
        dst[SWI(o + 3*s)]   = cmul(unpk(y[3]),  W3);
        dst[SWI(o + 4*s)]   = cmul(unpk(y[4]),  W4);
        dst[SWI(o + 5*s)]   = cmul(unpk(y[5]),  W5);
        dst[SWI(o + 6*s)]   = cmul(unpk(y[6]),  W6);
        dst[SWI(o + 7*s)]   = cmul(unpk(y[7]),  W7);
        dst[SWI(o + 8*s)]   = cmul(unpk(y[8]),  W8);
        dst[SWI(o + 9*s)]   = cmul(unpk(y[9]),  W9);
        dst[SWI(o + 10*s)]  = cmul(unpk(y[10]), W10);
        dst[SWI(o + 11*s)]  = cmul(unpk(y[11]), W11);
        dst[SWI(o + 12*s)]  = cmul(unpk(y[12]), W12);
        dst[SWI(o + 13*s)]  = cmul(unpk(y[13]), W13);
        dst[SWI(o + 14*s)]  = cmul(unpk(y[14]), W14);
        dst[SWI(o + 15*s)]  = cmul(unpk(y[15]), W15);
    }
}

// final radix-8 stage of the 2048 FFT (p==0, no twiddles): reads/writes t+256m
__device__ __forceinline__ void stage8_final(const float2* src, float2* dst, int t)
{
    u64c y[8];
    bf8_fwd(src, t, 256, y);
    store8_raw(dst, t, 256, y);
}

// ---------------- generic stage8 (fwd/inv) for the finalize kernel -----------
template<bool INV, bool NOTW>
__device__ __forceinline__ void stage8(const float2* __restrict__ src,
                                       float2* __restrict__ dst,
                                       const float2* __restrict__ tw,
                                       int sh, int ls, int eighth,
                                       int tid, int nt)
{
    const u64c CC2 = cc2_const();
    for (int t = tid; t < eighth; t += nt) {
        int p = t >> ls;
        int q = t & ((1 << ls) - 1);
        u64c x0 = *(const u64c*)&src[SWI(t)];
        u64c x1 = *(const u64c*)&src[SWI(t + eighth)];
        u64c x2 = *(const u64c*)&src[SWI(t + 2 * eighth)];
        u64c x3 = *(const u64c*)&src[SWI(t + 3 * eighth)];
        u64c x4 = *(const u64c*)&src[SWI(t + 4 * eighth)];
        u64c x5 = *(const u64c*)&src[SWI(t + 5 * eighth)];
        u64c x6 = *(const u64c*)&src[SWI(t + 6 * eighth)];
        u64c x7 = *(const u64c*)&src[SWI(t + 7 * eighth)];

        u64c u0 = cadd(x0, x4), u1 = csub(x0, x4);
        u64c u2 = cadd(x2, x6), u3 = csub(x2, x6);
        u64c e0 = cadd(u0, u2), e2 = csub(u0, u2);
        u64c j3 = cmuli(u3);
        u64c e1, e3;
        if (!INV) { e1 = csub(u1, j3); e3 = cadd(u1, j3); }
        else      { e1 = cadd(u1, j3); e3 = csub(u1, j3); }

        u64c v0 = cadd(x1, x5), v1 = csub(x1, x5);
        u64c v2 = cadd(x3, x7), v3 = csub(x3, x7);
        u64c o0 = cadd(v0, v2), o2 = csub(v0, v2);
        u64c k3 = cmuli(v3);
        u64c o1, o3;
        if (!INV) { o1 = csub(v1, k3); o3 = cadd(v1, k3); }
        else      { o1 = cadd(v1, k3); o3 = csub(v1, k3); }

        u64c t1, t2, t3;
        if (!INV) {
            t1 = w8m1(o1, CC2);
            t2 = cmulmi(o2);
            t3 = w8m3(o3, CC2);
        } else {
            t1 = cscale(cadd(o1, cmuli(o1)), CC2);
            t2 = cmuli(o2);
            t3 = cscale(cmuli(cadd(o3, cmuli(o3))), CC2);
        }
        u64c y0 = cadd(e0, o0), y4 = csub(e0, o0);
        u64c y1 = cadd(e1, t1), y5 = csub(e1, t1);
        u64c y2 = cadd(e2, t2), y6 = csub(e2, t2);
        u64c y3 = cadd(e3, t3), y7 = csub(e3, t3);

        int s = 1 << ls;
        int o = q + (p << (ls + 3));
        if (NOTW) {
            *(u64c*)&dst[SWI(o)]       = y0;
            *(u64c*)&dst[SWI(o + s)]   = y1;
            *(u64c*)&dst[SWI(o + 2*s)] = y2;
            *(u64c*)&dst[SWI(o + 3*s)] = y3;
            *(u64c*)&dst[SWI(o + 4*s)] = y4;
            *(u64c*)&dst[SWI(o + 5*s)] = y5;
            *(u64c*)&dst[SWI(o + 6*s)] = y6;
            *(u64c*)&dst[SWI(o + 7*s)] = y7;
        } else {
            float2 w1 = tw[p << sh];
            float2 w2 = tw[(2 * p) << sh];
            float2 w4 = tw[(4 * p) << sh];
            if (INV) { w1.y = -w1.y; w2.y = -w2.y; w4.y = -w4.y; }
            float2 w3 = cmul(w1, w2);
            float2 w5 = cmul(w1, w4);
            float2 w6 = cmul(w2, w4);
            float2 w7 = cmul(w3, w4);
            dst[SWI(o)]       = unpk(y0);
            dst[SWI(o + s)]   = cmul(unpk(y1), w1);
            dst[SWI(o + 2*s)] = cmul(unpk(y2), w2);
            dst[SWI(o + 3*s)] = cmul(unpk(y3), w3);
            dst[SWI(o + 4*s)] = cmul(unpk(y4), w4);
            dst[SWI(o + 5*s)] = cmul(unpk(y5), w5);
            dst[SWI(o + 6*s)] = cmul(unpk(y6), w6);
            dst[SWI(o + 7*s)] = cmul(unpk(y7), w7);
        }
    }
}

template<bool INV>
__device__ void fft4096_r8(float2* A, float2* B, const float2* tw, int tid, int nt)
{
    stage8<INV, false>(A, B, tw, 0, 0, 512, tid, nt); __syncthreads();
    stage8<INV, false>(B, A, tw, 3, 3, 512, tid, nt); __syncthreads();
    stage8<INV, false>(A, B, tw, 6, 6, 512, tid, nt); __syncthreads();
    stage8<INV, true >(B, A, tw, 9, 9, 512, tid, nt); __syncthreads();
}

// Unscaled bin product: returns 4*P2, 8*P3 (constants folded into finalize).
__device__ __forceinline__ void binprod(float2 Zk, float2 Zm, float2 Gk, float2 Gm,
                                        float2 w, float2& P2, float2& P3)
{
    float2 F0 = { Zk.x + Zm.x,  Zk.y - Zm.y };
    float2 F1 = { Zk.y + Zm.y, -(Zk.x - Zm.x) };
    float2 E  = { Gk.x + Gm.x,  Gk.y - Gm.y };
    float2 O  = { Gk.y + Gm.y, -(Gk.x - Gm.x) };
    float2 F2 = { E.x + w.x * O.x - w.y * O.y, E.y + w.x * O.y + w.y * O.x };
    P2 = cmul(F0, F1);
    P3 = cmul(P2, F2);
}

// Epilogue for one pixel: unpack spectra, accumulate products, zero A/Cc slots.
__device__ __forceinline__ void epilogue(float2* A, float2* Cc,
                                         const float2* __restrict__ tw, int tid,
                                         float2* a2, float2* a3)
{
    #pragma unroll
    for (int jj = 0; jj < 2; jj++) {
        int k  = tid + jj * 512;
        int km = (NFFT - k) & (NFFT - 1);
        int kb = 2048 - k;
        int jm = (NHALF - k) & (NHALF - 1);
        float2 Zk  = A[SWI(k)];
        float2 Zm  = A[SWI(km)];
        float2 Zk2 = A[SWI(kb)];
        float2 Zm2 = A[SWI(2048 + k)];
        float2 Gk  = Cc[SWI(k)];
        float2 Gm  = Cc[SWI(jm)];
        float2 w   = tw[k];
        float2 P2a, P3a, P2b, P3b;
        binprod(Zk,  Zm,  Gk, Gm, w, P2a, P3a);
        binprod(Zk2, Zm2, Gm, Gk, make_float2(-w.x, w.y), P2b, P3b);
        a2[2*jj].x   += P2a.x; a2[2*jj].y   += P2a.y;
        a3[2*jj].x   += P3a.x; a3[2*jj].y   += P3a.y;
        a2[2*jj+1].x += P2b.x; a2[2*jj+1].y += P2b.y;
        a3[2*jj+1].x += P3b.x; a3[2*jj+1].y += P3b.y;
        float2 z = make_float2(0.f, 0.f);
        A[SWI(k)] = z; A[SWI(km)] = z; A[SWI(kb)] = z; A[SWI(2048 + k)] = z;
        Cc[SWI(k)] = z; Cc[SWI(jm)] = z;
    }
    if (tid == 0) {                       // self-paired bin 1024
        float2 Zk = A[SWI(1024)], Zm = A[SWI(3072)];
        float2 Gk = Cc[SWI(1024)];
        float2 P2e, P3e;
        binprod(Zk, Zm, Gk, Gk, make_float2(0.f, -1.f), P2e, P3e);
        a2[4].x += P2e.x; a2[4].y += P2e.y;
        a3[4].x += P3e.x; a3[4].y += P3e.y;
        float2 z = make_float2(0.f, 0.f);
        A[SWI(1024)] = z; A[SWI(3072)] = z; Cc[SWI(1024)] = z;
    }
}

__global__ void zero_kernel()
{
    int i = blockIdx.x * blockDim.x + threadIdx.x;
    int n = NB * NSPEC * 2;
    if (i < n) {
        ((float*)g_acc2)[i] = 0.f;
        ((float*)g_acc3)[i] = 0.f;
    }
    if (i < NB * CCH) ((float*)g_first)[i] = 0.f;
}

__global__ void __launch_bounds__(NTHR, 1)
poly_sketch_kernel(const float* __restrict__ x,
                   const int* __restrict__ h_idx,
                   const int* __restrict__ s_bits)
{
    extern __shared__ float2 smem[];
    float2* tw = smem;                  // NTW
    float2* A1 = smem + NTW;            // APAD
    float2* B1 = A1 + APAD;
    float2* A2 = B1 + APAD;
    float2* B2 = A2 + APAD;
    float2* C1 = B2 + APAD;             // CPAD
    float2* D1 = C1 + CPAD;
    float2* C2 = D1 + CPAD;
    float2* D2 = C2 + CPAD;

    int tid  = threadIdx.x;
    int b    = blockIdx.x / SLOTS;
    int slot = blockIdx.x % SLOTS;

    for (int j = tid; j < NTW; j += NTHR) {
        float sn, cs;
        sincospif(-(float)j * (1.0f / 2048.0f), &sn, &cs);
        tw[j] = make_float2(cs, sn);
    }
    for (int j = tid; j < APAD; j += NTHR) {
        A1[j] = make_float2(0.f, 0.f);
        A2[j] = make_float2(0.f, 0.f);
    }
    for (int j = tid; j < CPAD; j += NTHR) {
        C1[j] = make_float2(0.f, 0.f);
        C2[j] = make_float2(0.f, 0.f);
    }

    int   h0 = h_idx[tid],          h1 = h_idx[CCH + tid],        h2 = h_idx[2 * CCH + tid];
    float s0 = (float)(2 * s_bits[tid] - 1);
    float s1 = (float)(2 * s_bits[CCH + tid] - 1);
    float s2 = (float)(2 * s_bits[2 * CCH + tid] - 1);
    int cfa = 2 * SWI(h2 >> 1) + (h2 & 1);
    __syncthreads();

    float2 a2[5], a3[5];
    #pragma unroll
    for (int i = 0; i < 5; i++) { a2[i] = make_float2(0.f, 0.f); a3[i] = make_float2(0.f, 0.f); }
    float xsum = 0.f;

    const float* xrow = x + (size_t)b * NPIX * CCH + tid;
    float xv1 = xrow[(size_t)slot * CCH];
    float xv2 = (slot + SLOTS < NPIX) ? xrow[(size_t)(slot + SLOTS) * CCH] : 0.f;

    // ping-pong roles: sA* = scatter/front buffer (zeroed), sB* = scratch.
    float2 *sA1 = A1, *sB1 = B1, *sA2 = A2, *sB2 = B2;
    float2 *sC1 = C1, *sD1 = D1, *sC2 = C2, *sD2 = D2;

    for (int pix = slot; pix < NPIX; pix += 2 * SLOTS) {
        atomicAdd(&sA1[SWI(h0)].x, xv1 * s0);
        atomicAdd(&sA1[SWI(h1)].y, xv1 * s1);
        atomicAdd(&((float*)sC1)[cfa], xv1 * s2);
        atomicAdd(&sA2[SWI(h0)].x, xv2 * s0);
        atomicAdd(&sA2[SWI(h1)].y, xv2 * s1);
        atomicAdd(&((float*)sC2)[cfa], xv2 * s2);
        xsum += xv1 + xv2;
        __syncthreads();

        // prefetch next pixel pair
        int n1 = pix + 2 * SLOTS, n2 = pix + 3 * SLOTS;
        float xn1 = (n1 < NPIX) ? xrow[(size_t)n1 * CCH] : 0.f;
        float xn2 = (n2 < NPIX) ? xrow[(size_t)n2 * CCH] : 0.f;

        // ---- phase 1: A radix-16 stage1 (ls=0, sh=0); C radix-16 stage1 (ls=0, sh=1)
        if (tid < 256) stage16<false>(sA1, sB1, tw, 0, 0, tid,       256);
        else           stage16<false>(sA2, sB2, tw, 0, 0, tid - 256, 256);
        if (tid < 128)       stage16<false>(sC1, sD1, tw, 1, 0, tid,       128);
        else if (tid < 256)  stage16<false>(sC2, sD2, tw, 1, 0, tid - 128, 128);
        __syncthreads();
        // ---- phase 2: A stage2 (ls=4, sh=4); C stage2 (ls=4, sh=5)
        if (tid < 256) stage16<false>(sB1, sA1, tw, 4, 4, tid,       256);
        else           stage16<false>(sB2, sA2, tw, 4, 4, tid - 256, 256);
        if (tid < 128)       stage16<false>(sD1, sC1, tw, 5, 4, tid,       128);
        else if (tid < 256)  stage16<false>(sD2, sC2, tw, 5, 4, tid - 128, 128);
        __syncthreads();
        // ---- phase 3: A stage3 notw (ls=8); C final radix-8 notw
        if (tid < 256) stage16<true>(sA1, sB1, tw, 0, 8, tid,       256);
        else           stage16<true>(sA2, sB2, tw, 0, 8, tid - 256, 256);
        if (tid < 256) stage8_final(sC1, sD1, tid);
        else           stage8_final(sC2, sD2, tid - 256);
        __syncthreads();
        // spectra: Z in sB*, G in sD*

        epilogue(sB1, sD1, tw, tid, a2, a3);    // reads + zeroes sB1/sD1
        epilogue(sB2, sD2, tw, tid, a2, a3);

        // swap roles: freshly-zeroed spectrum buffers become next scatter targets
        float2* t0;
        t0 = sA1; sA1 = sB1; sB1 = t0;
        t0 = sA2; sA2 = sB2; sB2 = t0;
        t0 = sC1; sC1 = sD1; sD1 = t0;
        t0 = sC2; sC2 = sD2; sD2 = t0;

        xv1 = xn1;
        xv2 = xn2;
        __syncthreads();
    }

    int bins[4] = { tid, 2048 - tid, tid + 512, 1536 - tid };
    #pragma unroll
    for (int i = 0; i < 4; i++) {
        atomicAdd(&g_acc2[b][bins[i]].x, a2[i].x);
        atomicAdd(&g_acc2[b][bins[i]].y, a2[i].y);
        atomicAdd(&g_acc3[b][bins[i]].x, a3[i].x);
        atomicAdd(&g_acc3[b][bins[i]].y, a3[i].y);
    }
    if (tid == 0) {
        atomicAdd(&g_acc2[b][1024].x, a2[4].x);
        atomicAdd(&g_acc2[b][1024].y, a2[4].y);
        atomicAdd(&g_acc3[b][1024].x, a3[4].x);
        atomicAdd(&g_acc3[b][1024].y, a3[4].y);
    }
    atomicAdd(&g_first[b][tid], xsum);
}

__global__ void __launch_bounds__(NTHR, 1)
finalize_kernel(const float* __restrict__ alpha, float* __restrict__ out)
{
    extern __shared__ float2 smem[];
    float2* tw  = smem;                 // NTW
    float2* A   = smem + NTW;
    float2* B   = A + APAD;
    float*  phi = (float*)(B + APAD);   // 8712 floats
    __shared__ float red[17];

    int tid = threadIdx.x;
    int b   = blockIdx.x;

    for (int j = tid; j < NTW; j += NTHR) {
        float sn, cs;
        sincospif(-(float)j * (1.0f / 2048.0f), &sn, &cs);
        tw[j] = make_float2(cs, sn);
    }
    __syncthreads();

    // accumulators carry 4x (acc2) and 8x (acc3) -> fold 0.25 / 0.125 here
    const float inv_n = 1.0f / ((float)NPIX * (float)NFFT);

    for (int i = tid; i < NFFT; i += NTHR) {
        if (i <= NHALF) A[SWI(i)] = g_acc2[b][i];
        else { float2 v = g_acc2[b][NFFT - i]; A[SWI(i)] = make_float2(v.x, -v.y); }
    }
    __syncthreads();
    fft4096_r8<true>(A, B, tw, tid, NTHR);
    {
        float a2c = alpha[2] * inv_n * 0.25f;
        for (int i = tid; i < NFFT; i += NTHR) phi[513 + i] = A[SWI(i)].x * a2c;
    }
    __syncthreads();

    for (int i = tid; i < NFFT; i += NTHR) {
        if (i <= NHALF) A[SWI(i)] = g_acc3[b][i];
        else { float2 v = g_acc3[b][NFFT - i]; A[SWI(i)] = make_float2(v.x, -v.y); }
    }
    __syncthreads();
    fft4096_r8<true>(A, B, tw, tid, NTHR);
    {
        float a3c = alpha[3] * inv_n * 0.125f;
        for (int i = tid; i < NFFT; i += NTHR) phi[513 + NFFT + i] = A[SWI(i)].x * a3c;
    }

    if (tid == 0) phi[0] = alpha[0];
    phi[1 + tid] = alpha[1] * g_first[b][tid] * (1.0f / (float)NPIX);
    __syncthreads();

    float lsum = 0.f;
    for (int i = tid; i < DOUT; i += NTHR) {
        float v = phi[i];
        float r;
        if (v > 0.f)      r =  sqrtf(v + 1e-12f);
        else if (v < 0.f) r = -sqrtf(-v + 1e-12f);
        else              r = 0.f;
        phi[i] = r;
        lsum += r * r;
    }
    #pragma unroll
    for (int off = 16; off > 0; off >>= 1)
        lsum += __shfl_down_sync(0xffffffffu, lsum, off);
    if ((tid & 31) == 0) red[tid >> 5] = lsum;
    __syncthreads();
    if (tid == 0) {
        float s = 0.f;
        #pragma unroll
        for (int k = 0; k < 16; k++) s += red[k];
        red[16] = 1.0f / sqrtf(s);
    }
    __syncthreads();
    float rn = red[16];
    for (int i = tid; i < DOUT; i += NTHR)
        out[(size_t)b * DOUT + i] = phi[i] * rn;
}

extern "C" void kernel_launch(void* const* d_in, const int* in_sizes, int n_in,
                              void* d_out, int out_size)
{
    const float* x     = (const float*)d_in[0];
    const float* alpha = (const float*)d_in[1];
    const int*   h     = (const int*)d_in[2];
    const int*   sb    = (const int*)d_in[3];
    float*       out   = (float*)d_out;

    const int MAIN_SMEM = (NTW + 4 * APAD + 4 * CPAD) * (int)sizeof(float2); // 219136
    const int FIN_SMEM  = (NTW + 2 * APAD) * (int)sizeof(float2) + 8712 * 4; // 118816

    cudaFuncSetAttribute(poly_sketch_kernel,
                         cudaFuncAttributeMaxDynamicSharedMemorySize, MAIN_SMEM);
    cudaFuncSetAttribute(finalize_kernel,
                         cudaFuncAttributeMaxDynamicSharedMemorySize, FIN_SMEM);

    zero_kernel<<<(NB * NSPEC * 2 + 255) / 256, 256>>>();
    poly_sketch_kernel<<<NB * SLOTS, NTHR, MAIN_SMEM>>>(x, h, sb);
    finalize_kernel<<<NB, NTHR, FIN_SMEM>>>(alpha, out);
}

// round 12
// speedup vs baseline: 2.6417x; 1.0179x over previous
#include <cuda_runtime.h>
#include <math.h>

#define NFFT   4096
#define NHALF  2048
#define NSPEC  2049
#define CCH    512
#define NPIX   784
#define NB     8
#define SLOTS  18
#define DOUT   8705
#define NTHR   256      // poly kernel threads (3 butterflies/thread/phase)
#define NTHF   512      // finalize kernel threads

#define NTW    2048     // twiddle table entries (all stage indices < 2048)
#define APAD   4224     // 4096 + 4096/32 padding
#define SWI(i) ((i) + ((i) >> 5))

__device__ float2 g_acc2[NB][NSPEC];
__device__ float2 g_acc3[NB][NSPEC];
__device__ float  g_first[NB][CCH];

typedef unsigned long long u64c;   // packed complex: lo = re, hi = im

__device__ __forceinline__ u64c cadd(u64c a, u64c b) {
    u64c r; asm("add.rn.f32x2 %0,%1,%2;" : "=l"(r) : "l"(a), "l"(b)); return r;
}
__device__ __forceinline__ u64c csub(u64c a, u64c b) {
    u64c r; asm("sub.rn.f32x2 %0,%1,%2;" : "=l"(r) : "l"(a), "l"(b)); return r;
}
__device__ __forceinline__ u64c cscale(u64c a, u64c k) {
    u64c r; asm("mul.rn.f32x2 %0,%1,%2;" : "=l"(r) : "l"(a), "l"(k)); return r;
}
__device__ __forceinline__ u64c cmuli(u64c a) {      // i*a = (-im, re)
    float x, y; asm("mov.b64 {%0,%1},%2;" : "=f"(x), "=f"(y) : "l"(a));
    float ny = -y;
    u64c r; asm("mov.b64 %0,{%1,%2};" : "=l"(r) : "f"(ny), "f"(x)); return r;
}
__device__ __forceinline__ u64c cmulmi(u64c a) {     // -i*a = (im, -re)
    float x, y; asm("mov.b64 {%0,%1},%2;" : "=f"(x), "=f"(y) : "l"(a));
    float nx = -x;
    u64c r; asm("mov.b64 %0,{%1,%2};" : "=l"(r) : "f"(y), "f"(nx)); return r;
}
__device__ __forceinline__ float2 unpk(u64c a) {
    float2 r; asm("mov.b64 {%0,%1},%2;" : "=f"(r.x), "=f"(r.y) : "l"(a)); return r;
}
__device__ __forceinline__ u64c pk2(float x, float y) {
    u64c r; asm("mov.b64 %0,{%1,%2};" : "=l"(r) : "f"(x), "f"(y)); return r;
}
__device__ __forceinline__ u64c cc2_const() {        // {CC, CC}
    u64c r; float c = 0.70710678118654752f;
    asm("mov.b64 %0,{%1,%1};" : "=l"(r) : "f"(c)); return r;
}

__device__ __forceinline__ float2 cmul(float2 a, float2 b) {
    return make_float2(a.x * b.x - a.y * b.y, a.x * b.y + a.y * b.x);
}
__device__ __forceinline__ u64c cmulc(u64c z, float wr, float wi) {
    float2 a = unpk(z);
    return pk2(a.x * wr - a.y * wi, a.x * wi + a.y * wr);
}
__device__ __forceinline__ u64c w8m1(u64c z, u64c CC2) {  // z * w8^1
    return cscale(cadd(z, cmulmi(z)), CC2);
}
__device__ __forceinline__ u64c w8m3(u64c z, u64c CC2) {  // z * w8^3
    return cscale(csub(cmulmi(z), z), CC2);
}

// ---------------- DFT16 core: loads 16 strided cells, returns y[16] ----------
__device__ __forceinline__ void bf16_fwd(const float2* __restrict__ src,
                                         int t, u64c* __restrict__ y)
{
    const u64c CC2 = cc2_const();
    const float c1 = 0.92387953251128674f, s1 = 0.38268343236508977f;
    u64c u[4][4];
    #pragma unroll
    for (int j = 0; j < 4; j++) {
        u64c a = *(const u64c*)&src[SWI(t + j * 256)];
        u64c b = *(const u64c*)&src[SWI(t + (j + 4) * 256)];
        u64c c = *(const u64c*)&src[SWI(t + (j + 8) * 256)];
        u64c d = *(const u64c*)&src[SWI(t + (j + 12) * 256)];
        u64c apc = cadd(a, c), amc = csub(a, c);
        u64c bpd = cadd(b, d);
        u64c jb  = cmuli(csub(b, d));
        u[j][0] = cadd(apc, bpd);
        u[j][1] = csub(amc, jb);
        u[j][2] = csub(apc, bpd);
        u[j][3] = cadd(amc, jb);
    }
    u[1][1] = cmulc(u[1][1],  c1, -s1);
    u[1][2] = w8m1(u[1][2], CC2);
    u[1][3] = cmulc(u[1][3],  s1, -c1);
    u[2][1] = w8m1(u[2][1], CC2);
    u[2][2] = cmulmi(u[2][2]);
    u[2][3] = w8m3(u[2][3], CC2);
    u[3][1] = cmulc(u[3][1],  s1, -c1);
    u[3][2] = w8m3(u[3][2], CC2);
    u[3][3] = cmulc(u[3][3], -c1,  s1);
    #pragma unroll
    for (int a = 0; a < 4; a++) {
        u64c p0 = u[0][a], p1 = u[1][a], p2 = u[2][a], p3 = u[3][a];
        u64c q0 = cadd(p0, p2), q1 = csub(p0, p2);
        u64c q2 = cadd(p1, p3);
        u64c jq = cmuli(csub(p1, p3));
        y[a]      = cadd(q0, q2);
        y[a + 4]  = csub(q1, jq);
        y[a + 8]  = csub(q0, q2);
        y[a + 12] = cadd(q1, jq);
    }
}

// Triple radix-16 stage: same butterfly index for 3 FFTs, shared twiddles.
template<bool NOTW>
__device__ __forceinline__ void stage16_tri(const float2* s0, float2* d0,
                                            const float2* s1, float2* d1,
                                            const float2* s2, float2* d2,
                                            const float2* __restrict__ tw,
                                            int sh, int ls, int t)
{
    int p = t >> ls;
    int q = t & ((1 << ls) - 1);
    int s = 1 << ls;
    int o = q + (p << (ls + 4));
    float2 W1, W2, W3, W4, W5, W6, W7, W8, W9, W10, W11, W12, W13, W14, W15;
    if (!NOTW) {
        W1 = tw[p << sh];
        W2 = tw[(2 * p) << sh];
        W4 = tw[(4 * p) << sh];
        W8 = tw[(8 * p) << sh];
        W3  = cmul(W1, W2);  W5  = cmul(W1, W4);  W6  = cmul(W2, W4);
        W7  = cmul(W3, W4);  W9  = cmul(W1, W8);  W10 = cmul(W2, W8);
        W11 = cmul(W3, W8);  W12 = cmul(W4, W8);  W13 = cmul(W5, W8);
        W14 = cmul(W6, W8);  W15 = cmul(W7, W8);
    }
    const float2* srcs[3] = { s0, s1, s2 };
    float2* dsts[3] = { d0, d1, d2 };
    #pragma unroll
    for (int f = 0; f < 3; f++) {
        u64c y[16];
        bf16_fwd(srcs[f], t, y);
        float2* dst = dsts[f];
        if (NOTW) {
            #pragma unroll
            for (int m = 0; m < 16; m++)
                *(u64c*)&dst[SWI(o + m * s)] = y[m];
        } else {
            dst[SWI(o)]        = unpk(y[0]);
            dst[SWI(o + s)]    = cmul(unpk(y[1]),  W1);
            dst[SWI(o + 2*s)]  = cmul(unpk(y[2]),  W2);
            dst[SWI(o + 3*s)]  = cmul(unpk(y[3]),  W3);
            dst[SWI(o + 4*s)]  = cmul(unpk(y[4]),  W4);
            dst[SWI(o + 5*s)]  = cmul(unpk(y[5]),  W5);
            dst[SWI(o + 6*s)]  = cmul(unpk(y[6]),  W6);
            dst[SWI(o + 7*s)]  = cmul(unpk(y[7]),  W7);
            dst[SWI(o + 8*s)]  = cmul(unpk(y[8]),  W8);
            dst[SWI(o + 9*s)]  = cmul(unpk(y[9]),  W9);
            dst[SWI(o + 10*s)] = cmul(unpk(y[10]), W10);
            dst[SWI(o + 11*s)] = cmul(unpk(y[11]), W11);
            dst[SWI(o + 12*s)] = cmul(unpk(y[12]), W12);
            dst[SWI(o + 13*s)] = cmul(unpk(y[13]), W13);
            dst[SWI(o + 14*s)] = cmul(unpk(y[14]), W14);
            dst[SWI(o + 15*s)] = cmul(unpk(y[15]), W15);
        }
    }
}

// ---------------- generic stage8 (fwd/inv) for the finalize kernel -----------
template<bool INV, bool NOTW>
__device__ __forceinline__ void stage8(const float2* __restrict__ src,
                                       float2* __restrict__ dst,
                                       const float2* __restrict__ tw,
                                       int sh, int ls, int eighth,
                                       int tid, int nt)
{
    const u64c CC2 = cc2_const();
    for (int t = tid; t < eighth; t += nt) {
        int p = t >> ls;
        int q = t & ((1 << ls) - 1);
        u64c x0 = *(const u64c*)&src[SWI(t)];
        u64c x1 = *(const u64c*)&src[SWI(t + eighth)];
        u64c x2 = *(const u64c*)&src[SWI(t + 2 * eighth)];
        u64c x3 = *(const u64c*)&src[SWI(t + 3 * eighth)];
        u64c x4 = *(const u64c*)&src[SWI(t + 4 * eighth)];
        u64c x5 = *(const u64c*)&src[SWI(t + 5 * eighth)];
        u64c x6 = *(const u64c*)&src[SWI(t + 6 * eighth)];
        u64c x7 = *(const u64c*)&src[SWI(t + 7 * eighth)];

        u64c u0 = cadd(x0, x4), u1 = csub(x0, x4);
        u64c u2 = cadd(x2, x6), u3 = csub(x2, x6);
        u64c e0 = cadd(u0, u2), e2 = csub(u0, u2);
        u64c j3 = cmuli(u3);
        u64c e1, e3;
        if (!INV) { e1 = csub(u1, j3); e3 = cadd(u1, j3); }
        else      { e1 = cadd(u1, j3); e3 = csub(u1, j3); }

        u64c v0 = cadd(x1, x5), v1 = csub(x1, x5);
        u64c v2 = cadd(x3, x7), v3 = csub(x3, x7);
        u64c o0 = cadd(v0, v2), o2 = csub(v0, v2);
        u64c k3 = cmuli(v3);
        u64c o1, o3;
        if (!INV) { o1 = csub(v1, k3); o3 = cadd(v1, k3); }
        else      { o1 = cadd(v1, k3); o3 = csub(v1, k3); }

        u64c t1, t2, t3;
        if (!INV) {
            t1 = w8m1(o1, CC2);
            t2 = cmulmi(o2);
            t3 = w8m3(o3, CC2);
        } else {
            t1 = cscale(cadd(o1, cmuli(o1)), CC2);
            t2 = cmuli(o2);
            t3 = cscale(cmuli(cadd(o3, cmuli(o3))), CC2);
        }
        u64c y0 = cadd(e0, o0), y4 = csub(e0, o0);
        u64c y1 = cadd(e1, t1), y5 = csub(e1, t1);
        u64c y2 = cadd(e2, t2), y6 = csub(e2, t2);
        u64c y3 = cadd(e3, t3), y7 = csub(e3, t3);

        int s = 1 << ls;
        int o = q + (p << (ls + 3));
        if (NOTW) {
            *(u64c*)&dst[SWI(o)]       = y0;
            *(u64c*)&dst[SWI(o + s)]   = y1;
            *(u64c*)&dst[SWI(o + 2*s)] = y2;
            *(u64c*)&dst[SWI(o + 3*s)] = y3;
            *(u64c*)&dst[SWI(o + 4*s)] = y4;
            *(u64c*)&dst[SWI(o + 5*s)] = y5;
            *(u64c*)&dst[SWI(o + 6*s)] = y6;
            *(u64c*)&dst[SWI(o + 7*s)] = y7;
        } else {
            float2 w1 = tw[p << sh];
            float2 w2 = tw[(2 * p) << sh];
            float2 w4 = tw[(4 * p) << sh];
            if (INV) { w1.y = -w1.y; w2.y = -w2.y; w4.y = -w4.y; }
            float2 w3 = cmul(w1, w2);
            float2 w5 = cmul(w1, w4);
            float2 w6 = cmul(w2, w4);
            float2 w7 = cmul(w3, w4);
            dst[SWI(o)]       = unpk(y0);
            dst[SWI(o + s)]   = cmul(unpk(y1), w1);
            dst[SWI(o + 2*s)] = cmul(unpk(y2), w2);
            dst[SWI(o + 3*s)] = cmul(unpk(y3), w3);
            dst[SWI(o + 4*s)] = cmul(unpk(y4), w4);
            dst[SWI(o + 5*s)] = cmul(unpk(y5), w5);
            dst[SWI(o + 6*s)] = cmul(unpk(y6), w6);
            dst[SWI(o + 7*s)] = cmul(unpk(y7), w7);
        }
    }
}

template<bool INV>
__device__ void fft4096_r8(float2* A, float2* B, const float2* tw, int tid, int nt)
{
    stage8<INV, false>(A, B, tw, 0, 0, 512, tid, nt); __syncthreads();
    stage8<INV, false>(B, A, tw, 3, 3, 512, tid, nt); __syncthreads();
    stage8<INV, false>(A, B, tw, 6, 6, 512, tid, nt); __syncthreads();
    stage8<INV, true >(B, A, tw, 9, 9, 512, tid, nt); __syncthreads();
}

// Hermitian unpack (2x-scaled): Z = R + i*I with R,I real spectra.
__device__ __forceinline__ void unpack2(float2 Zk, float2 Zm, float2& R, float2& I)
{
    R = make_float2(Zk.x + Zm.x,  Zk.y - Zm.y);
    I = make_float2(Zk.y + Zm.y, -(Zk.x - Zm.x));
}

__global__ void zero_kernel()
{
    int i = blockIdx.x * blockDim.x + threadIdx.x;
    int n = NB * NSPEC * 2;
    if (i < n) {
        ((float*)g_acc2)[i] = 0.f;
        ((float*)g_acc3)[i] = 0.f;
    }
    if (i < NB * CCH) ((float*)g_first)[i] = 0.f;
}

__global__ void __launch_bounds__(NTHR, 1)
poly_sketch_kernel(const float* __restrict__ x,
                   const int* __restrict__ h_idx,
                   const int* __restrict__ s_bits)
{
    extern __shared__ float2 smem[];
    float2* tw = smem;                  // NTW
    float2* A1 = smem + NTW;            // pixel1 Z buffers
    float2* B1 = A1 + APAD;
    float2* A2 = B1 + APAD;             // pixel2 Z buffers
    float2* B2 = A2 + APAD;
    float2* AD = B2 + APAD;             // packed s2(p1) + i*s2(p2)
    float2* BD = AD + APAD;

    int tid  = threadIdx.x;
    int b    = blockIdx.x / SLOTS;
    int slot = blockIdx.x % SLOTS;

    for (int j = tid; j < NTW; j += NTHR) {
        float sn, cs;
        sincospif(-(float)j * (1.0f / 2048.0f), &sn, &cs);
        tw[j] = make_float2(cs, sn);
    }
    for (int j = tid; j < APAD; j += NTHR) {
        A1[j] = make_float2(0.f, 0.f);
        A2[j] = make_float2(0.f, 0.f);
        AD[j] = make_float2(0.f, 0.f);
    }

    // two channels per thread
    int ca = tid, cb = tid + 256;
    int   h0a = h_idx[ca],           h1a = h_idx[CCH + ca],        h2a = h_idx[2 * CCH + ca];
    int   h0b = h_idx[cb],           h1b = h_idx[CCH + cb],        h2b = h_idx[2 * CCH + cb];
    float s0a = (float)(2 * s_bits[ca] - 1);
    float s1a = (float)(2 * s_bits[CCH + ca] - 1);
    float s2a = (float)(2 * s_bits[2 * CCH + ca] - 1);
    float s0b = (float)(2 * s_bits[cb] - 1);
    float s1b = (float)(2 * s_bits[CCH + cb] - 1);
    float s2b = (float)(2 * s_bits[2 * CCH + cb] - 1);
    __syncthreads();

    float2 a2[8], a3[8], m2, m3;
    #pragma unroll
    for (int i = 0; i < 8; i++) { a2[i] = make_float2(0.f, 0.f); a3[i] = make_float2(0.f, 0.f); }
    m2 = make_float2(0.f, 0.f); m3 = make_float2(0.f, 0.f);
    float xsa = 0.f, xsb = 0.f;

    const float* xra = x + (size_t)b * NPIX * CCH + ca;
    const float* xrb = x + (size_t)b * NPIX * CCH + cb;
    float x1a = xra[(size_t)slot * CCH];
    float x1b = xrb[(size_t)slot * CCH];
    float x2a = (slot + SLOTS < NPIX) ? xra[(size_t)(slot + SLOTS) * CCH] : 0.f;
    float x2b = (slot + SLOTS < NPIX) ? xrb[(size_t)(slot + SLOTS) * CCH] : 0.f;

    float2 *sA1 = A1, *sB1 = B1, *sA2 = A2, *sB2 = B2, *sAD = AD, *sBD = BD;

    for (int pix = slot; pix < NPIX; pix += 2 * SLOTS) {
        // scatter: pixel1 -> sA1 (orders 0,1) + sAD.x (order 2); pixel2 -> sA2 / sAD.y
        atomicAdd(&sA1[SWI(h0a)].x, x1a * s0a);
        atomicAdd(&sA1[SWI(h1a)].y, x1a * s1a);
        atomicAdd(&sA1[SWI(h0b)].x, x1b * s0b);
        atomicAdd(&sA1[SWI(h1b)].y, x1b * s1b);
        atomicAdd(&sA2[SWI(h0a)].x, x2a * s0a);
        atomicAdd(&sA2[SWI(h1a)].y, x2a * s1a);
        atomicAdd(&sA2[SWI(h0b)].x, x2b * s0b);
        atomicAdd(&sA2[SWI(h1b)].y, x2b * s1b);
        atomicAdd(&sAD[SWI(h2a)].x, x1a * s2a);
        atomicAdd(&sAD[SWI(h2b)].x, x1b * s2b);
        atomicAdd(&sAD[SWI(h2a)].y, x2a * s2a);
        atomicAdd(&sAD[SWI(h2b)].y, x2b * s2b);
        xsa += x1a + x2a;
        xsb += x1b + x2b;
        __syncthreads();

        int n1 = pix + 2 * SLOTS, n2 = pix + 3 * SLOTS;
        float xn1a = (n1 < NPIX) ? xra[(size_t)n1 * CCH] : 0.f;
        float xn1b = (n1 < NPIX) ? xrb[(size_t)n1 * CCH] : 0.f;
        float xn2a = (n2 < NPIX) ? xra[(size_t)n2 * CCH] : 0.f;
        float xn2b = (n2 < NPIX) ? xrb[(size_t)n2 * CCH] : 0.f;

        stage16_tri<false>(sA1, sB1, sA2, sB2, sAD, sBD, tw, 0, 0, tid);
        __syncthreads();
        stage16_tri<false>(sB1, sA1, sB2, sA2, sBD, sAD, tw, 4, 4, tid);
        __syncthreads();
        stage16_tri<true>(sA1, sB1, sA2, sB2, sAD, sBD, tw, 0, 8, tid);
        __syncthreads();
        // spectra: Z1 in sB1, Z2 in sB2, Dspec in sBD

        #pragma unroll
        for (int jj = 0; jj < 4; jj++) {
            int k  = tid + jj * 256;               // 0..1023
            int km = (NFFT - k) & (NFFT - 1);
            int kb = 2048 - k;
            int kc = 2048 + k;
            float2 Z1k = sB1[SWI(k)],  Z1m = sB1[SWI(km)];
            float2 Z1b = sB1[SWI(kb)], Z1c = sB1[SWI(kc)];
            float2 Z2k = sB2[SWI(k)],  Z2m = sB2[SWI(km)];
            float2 Z2b = sB2[SWI(kb)], Z2c = sB2[SWI(kc)];
            float2 Dk  = sBD[SWI(k)],  Dm  = sBD[SWI(km)];
            float2 Db  = sBD[SWI(kb)], Dc  = sBD[SWI(kc)];

            float2 F0, F1, G0, G1, H0, H1;
            unpack2(Z1k, Z1m, F0, F1);
            unpack2(Z2k, Z2m, G0, G1);
            unpack2(Dk,  Dm,  H0, H1);
            float2 P2 = cmul(F0, F1), P3 = cmul(P2, H0);
            float2 Q2 = cmul(G0, G1), Q3 = cmul(Q2, H1);
            a2[2*jj].x += P2.x + Q2.x; a2[2*jj].y += P2.y + Q2.y;
            a3[2*jj].x += P3.x + Q3.x; a3[2*jj].y += P3.y + Q3.y;

            unpack2(Z1b, Z1c, F0, F1);
            unpack2(Z2b, Z2c, G0, G1);
            unpack2(Db,  Dc,  H0, H1);
            P2 = cmul(F0, F1); P3 = cmul(P2, H0);
            Q2 = cmul(G0, G1); Q3 = cmul(Q2, H1);
            a2[2*jj+1].x += P2.x + Q2.x; a2[2*jj+1].y += P2.y + Q2.y;
            a3[2*jj+1].x += P3.x + Q3.x; a3[2*jj+1].y += P3.y + Q3.y;

            float2 z = make_float2(0.f, 0.f);
            sB1[SWI(k)] = z; sB1[SWI(km)] = z; sB1[SWI(kb)] = z; sB1[SWI(kc)] = z;
            sB2[SWI(k)] = z; sB2[SWI(km)] = z; sB2[SWI(kb)] = z; sB2[SWI(kc)] = z;
            sBD[SWI(k)] = z; sBD[SWI(km)] = z; sBD[SWI(kb)] = z; sBD[SWI(kc)] = z;
        }
        if (tid == 0) {                       // self-paired bin 1024
            float2 Z1k = sB1[SWI(1024)], Z1m = sB1[SWI(3072)];
            float2 Z2k = sB2[SWI(1024)], Z2m = sB2[SWI(3072)];
            float2 Dk  = sBD[SWI(1024)], Dm  = sBD[SWI(3072)];
            float2 F0, F1, G0, G1, H0, H1;
            unpack2(Z1k, Z1m, F0, F1);
            unpack2(Z2k, Z2m, G0, G1);
            unpack2(Dk,  Dm,  H0, H1);
            float2 P2 = cmul(F0, F1), P3 = cmul(P2, H0);
            float2 Q2 = cmul(G0, G1), Q3 = cmul(Q2, H1);
            m2.x += P2.x + Q2.x; m2.y += P2.y + Q2.y;
            m3.x += P3.x + Q3.x; m3.y += P3.y + Q3.y;
            float2 z = make_float2(0.f, 0.f);
            sB1[SWI(1024)] = z; sB1[SWI(3072)] = z;
            sB2[SWI(1024)] = z; sB2[SWI(3072)] = z;
            sBD[SWI(1024)] = z; sBD[SWI(3072)] = z;
        }

        // swap: freshly-zeroed spectrum buffers become next scatter targets
        float2* t0;
        t0 = sA1; sA1 = sB1; sB1 = t0;
        t0 = sA2; sA2 = sB2; sB2 = t0;
        t0 = sAD; sAD = sBD; sBD = t0;

        x1a = xn1a; x1b = xn1b; x2a = xn2a; x2b = xn2b;
        __syncthreads();
    }

    #pragma unroll
    for (int jj = 0; jj < 4; jj++) {
        int binA = tid + jj * 256;
        int binB = 2048 - binA;
        atomicAdd(&g_acc2[b][binA].x, a2[2*jj].x);
        atomicAdd(&g_acc2[b][binA].y, a2[2*jj].y);
        atomicAdd(&g_acc3[b][binA].x, a3[2*jj].x);
        atomicAdd(&g_acc3[b][binA].y, a3[2*jj].y);
        atomicAdd(&g_acc2[b][binB].x, a2[2*jj+1].x);
        atomicAdd(&g_acc2[b][binB].y, a2[2*jj+1].y);
        atomicAdd(&g_acc3[b][binB].x, a3[2*jj+1].x);
        atomicAdd(&g_acc3[b][binB].y, a3[2*jj+1].y);
    }
    if (tid == 0) {
        atomicAdd(&g_acc2[b][1024].x, m2.x);
        atomicAdd(&g_acc2[b][1024].y, m2.y);
        atomicAdd(&g_acc3[b][1024].x, m3.x);
        atomicAdd(&g_acc3[b][1024].y, m3.y);
    }
    atomicAdd(&g_first[b][ca], xsa);
    atomicAdd(&g_first[b][cb], xsb);
}

__global__ void __launch_bounds__(NTHF, 1)
finalize_kernel(const float* __restrict__ alpha, float* __restrict__ out)
{
    extern __shared__ float2 smem[];
    float2* tw  = smem;                 // NTW
    float2* A   = smem + NTW;
    float2* B   = A + APAD;
    float*  phi = (float*)(B + APAD);   // 8712 floats
    __shared__ float red[17];

    int tid = threadIdx.x;
    int b   = blockIdx.x;

    for (int j = tid; j < NTW; j += NTHF) {
        float sn, cs;
        sincospif(-(float)j * (1.0f / 2048.0f), &sn, &cs);
        tw[j] = make_float2(cs, sn);
    }
    __syncthreads();

    // accumulators carry 4x (acc2) and 8x (acc3) -> fold 0.25 / 0.125 here
    const float inv_n = 1.0f / ((float)NPIX * (float)NFFT);

    for (int i = tid; i < NFFT; i += NTHF) {
        if (i <= NHALF) A[SWI(i)] = g_acc2[b][i];
        else { float2 v = g_acc2[b][NFFT - i]; A[SWI(i)] = make_float2(v.x, -v.y); }
    }
    __syncthreads();
    fft4096_r8<true>(A, B, tw, tid, NTHF);
    {
        float a2c = alpha[2] * inv_n * 0.25f;
        for (int i = tid; i < NFFT; i += NTHF) phi[513 + i] = A[SWI(i)].x * a2c;
    }
    __syncthreads();

    for (int i = tid; i < NFFT; i += NTHF) {
        if (i <= NHALF) A[SWI(i)] = g_acc3[b][i];
        else { float2 v = g_acc3[b][NFFT - i]; A[SWI(i)] = make_float2(v.x, -v.y); }
    }
    __syncthreads();
    fft4096_r8<true>(A, B, tw, tid, NTHF);
    {
        float a3c = alpha[3] * inv_n * 0.125f;
        for (int i = tid; i < NFFT; i += NTHF) phi[513 + NFFT + i] = A[SWI(i)].x * a3c;
    }

    if (tid == 0) phi[0] = alpha[0];
    phi[1 + tid] = alpha[1] * g_first[b][tid] * (1.0f / (float)NPIX);
    __syncthreads();

    float lsum = 0.f;
    for (int i = tid; i < DOUT; i += NTHF) {
        float v = phi[i];
        float r;
        if (v > 0.f)      r =  sqrtf(v + 1e-12f);
        else if (v < 0.f) r = -sqrtf(-v + 1e-12f);
        else              r = 0.f;
        phi[i] = r;
        lsum += r * r;
    }
    #pragma unroll
    for (int off = 16; off > 0; off >>= 1)
        lsum += __shfl_down_sync(0xffffffffu, lsum, off);
    if ((tid & 31) == 0) red[tid >> 5] = lsum;
    __syncthreads();
    if (tid == 0) {
        float s = 0.f;
        #pragma unroll
        for (int k = 0; k < 16; k++) s += red[k];
        red[16] = 1.0f / sqrtf(s);
    }
    __syncthreads();
    float rn = red[16];
    for (int i = tid; i < DOUT; i += NTHF)
        out[(size_t)b * DOUT + i] = phi[i] * rn;
}

extern "C" void kernel_launch(void* const* d_in, const int* in_sizes, int n_in,
                              void* d_out, int out_size)
{
    const float* x     = (const float*)d_in[0];
    const float* alpha = (const float*)d_in[1];
    const int*   h     = (const int*)d_in[2];
    const int*   sb    = (const int*)d_in[3];
    float*       out   = (float*)d_out;

    const int MAIN_SMEM = (NTW + 6 * APAD) * (int)sizeof(float2);            // 219136
    const int FIN_SMEM  = (NTW + 2 * APAD) * (int)sizeof(float2) + 8712 * 4; // 118816

    cudaFuncSetAttribute(poly_sketch_kernel,
                         cudaFuncAttributeMaxDynamicSharedMemorySize, MAIN_SMEM);
    cudaFuncSetAttribute(finalize_kernel,
                         cudaFuncAttributeMaxDynamicSharedMemorySize, FIN_SMEM);

    zero_kernel<<<(NB * NSPEC * 2 + 255) / 256, 256>>>();
    poly_sketch_kernel<<<NB * SLOTS, NTHR, MAIN_SMEM>>>(x, h, sb);
    finalize_kernel<<<NB, NTHF, FIN_SMEM>>>(alpha, out);
}

// round 13
// speedup vs baseline: 2.6921x; 1.0191x over previous
#include <cuda_runtime.h>
#include <math.h>

#define NFFT   4096
#define NHALF  2048
#define NSPEC  2049
#define CCH    512
#define NPIX   784
#define NB     8
#define SLOTS  18
#define DOUT   8705
#define NTHR   512
#define NTHF   512

#define NTW    2048     // twiddle table entries (all stage indices < 2048)
#define APAD   4224     // 4096 + 4096/32 padding
#define SWI(i) ((i) + ((i) >> 5))

__device__ float2 g_acc2[NB][NSPEC];
__device__ float2 g_acc3[NB][NSPEC];
__device__ float  g_first[NB][CCH];

typedef unsigned long long u64c;   // packed complex: lo = re, hi = im

__device__ __forceinline__ u64c cadd(u64c a, u64c b) {
    u64c r; asm("add.rn.f32x2 %0,%1,%2;" : "=l"(r) : "l"(a), "l"(b)); return r;
}
__device__ __forceinline__ u64c csub(u64c a, u64c b) {
    u64c r; asm("sub.rn.f32x2 %0,%1,%2;" : "=l"(r) : "l"(a), "l"(b)); return r;
}
__device__ __forceinline__ u64c cscale(u64c a, u64c k) {
    u64c r; asm("mul.rn.f32x2 %0,%1,%2;" : "=l"(r) : "l"(a), "l"(k)); return r;
}
__device__ __forceinline__ u64c cmuli(u64c a) {      // i*a = (-im, re)
    float x, y; asm("mov.b64 {%0,%1},%2;" : "=f"(x), "=f"(y) : "l"(a));
    float ny = -y;
    u64c r; asm("mov.b64 %0,{%1,%2};" : "=l"(r) : "f"(ny), "f"(x)); return r;
}
__device__ __forceinline__ u64c cmulmi(u64c a) {     // -i*a = (im, -re)
    float x, y; asm("mov.b64 {%0,%1},%2;" : "=f"(x), "=f"(y) : "l"(a));
    float nx = -x;
    u64c r; asm("mov.b64 %0,{%1,%2};" : "=l"(r) : "f"(y), "f"(nx)); return r;
}
__device__ __forceinline__ float2 unpk(u64c a) {
    float2 r; asm("mov.b64 {%0,%1},%2;" : "=f"(r.x), "=f"(r.y) : "l"(a)); return r;
}
__device__ __forceinline__ u64c pk2(float x, float y) {
    u64c r; asm("mov.b64 %0,{%1,%2};" : "=l"(r) : "f"(x), "f"(y)); return r;
}
__device__ __forceinline__ u64c cc2_const() {        // {CC, CC}
    u64c r; float c = 0.70710678118654752f;
    asm("mov.b64 %0,{%1,%1};" : "=l"(r) : "f"(c)); return r;
}

__device__ __forceinline__ float2 cmul(float2 a, float2 b) {
    return make_float2(a.x * b.x - a.y * b.y, a.x * b.y + a.y * b.x);
}
__device__ __forceinline__ u64c cmulc(u64c z, float wr, float wi) {
    float2 a = unpk(z);
    return pk2(a.x * wr - a.y * wi, a.x * wi + a.y * wr);
}
__device__ __forceinline__ u64c w8m1(u64c z, u64c CC2) {  // z * w8^1
    return cscale(cadd(z, cmulmi(z)), CC2);
}
__device__ __forceinline__ u64c w8m3(u64c z, u64c CC2) {  // z * w8^3
    return cscale(csub(cmulmi(z), z), CC2);
}

// ---------------- DFT16 core: loads 16 strided cells, returns y[16] ----------
__device__ __forceinline__ void bf16_fwd(const float2* __restrict__ src,
                                         int t, u64c* __restrict__ y)
{
    const u64c CC2 = cc2_const();
    const float c1 = 0.92387953251128674f, s1 = 0.38268343236508977f;
    u64c u[4][4];
    #pragma unroll
    for (int j = 0; j < 4; j++) {
        u64c a = *(const u64c*)&src[SWI(t + j * 256)];
        u64c b = *(const u64c*)&src[SWI(t + (j + 4) * 256)];
        u64c c = *(const u64c*)&src[SWI(t + (j + 8) * 256)];
        u64c d = *(const u64c*)&src[SWI(t + (j + 12) * 256)];
        u64c apc = cadd(a, c), amc = csub(a, c);
        u64c bpd = cadd(b, d);
        u64c jb  = cmuli(csub(b, d));
        u[j][0] = cadd(apc, bpd);
        u[j][1] = csub(amc, jb);
        u[j][2] = csub(apc, bpd);
        u[j][3] = cadd(amc, jb);
    }
    u[1][1] = cmulc(u[1][1],  c1, -s1);
    u[1][2] = w8m1(u[1][2], CC2);
    u[1][3] = cmulc(u[1][3],  s1, -c1);
    u[2][1] = w8m1(u[2][1], CC2);
    u[2][2] = cmulmi(u[2][2]);
    u[2][3] = w8m3(u[2][3], CC2);
    u[3][1] = cmulc(u[3][1],  s1, -c1);
    u[3][2] = w8m3(u[3][2], CC2);
    u[3][3] = cmulc(u[3][3], -c1,  s1);
    #pragma unroll
    for (int a = 0; a < 4; a++) {
        u64c p0 = u[0][a], p1 = u[1][a], p2 = u[2][a], p3 = u[3][a];
        u64c q0 = cadd(p0, p2), q1 = csub(p0, p2);
        u64c q2 = cadd(p1, p3);
        u64c jq = cmuli(csub(p1, p3));
        y[a]      = cadd(q0, q2);
        y[a + 4]  = csub(q1, jq);
        y[a + 8]  = csub(q0, q2);
        y[a + 12] = cadd(q1, jq);
    }
}

__device__ __forceinline__ void store16_tw(float2* __restrict__ dst, int o, int s,
                                           const u64c* __restrict__ y,
                                           const float2* W)
{
    dst[SWI(o)] = unpk(y[0]);
    #pragma unroll
    for (int m = 1; m < 16; m++)
        dst[SWI(o + m * s)] = cmul(unpk(y[m]), W[m - 1]);
}
__device__ __forceinline__ void store16_raw(float2* __restrict__ dst, int o, int s,
                                            const u64c* __restrict__ y)
{
    #pragma unroll
    for (int m = 0; m < 16; m++)
        *(u64c*)&dst[SWI(o + m * s)] = y[m];
}

__device__ __forceinline__ void build_W(const float2* __restrict__ tw,
                                        int p, int sh, float2* W)
{
    float2 W1 = tw[p << sh];
    float2 W2 = tw[(2 * p) << sh];
    float2 W4 = tw[(4 * p) << sh];
    float2 W8 = tw[(8 * p) << sh];
    W[0] = W1; W[1] = W2; W[2] = cmul(W1, W2); W[3] = W4;
    W[4] = cmul(W1, W4); W[5] = cmul(W2, W4); W[6] = cmul(W[2], W4);
    W[7] = W8; W[8] = cmul(W1, W8); W[9] = cmul(W2, W8);
    W[10] = cmul(W[2], W8); W[11] = cmul(W4, W8); W[12] = cmul(W[4], W8);
    W[13] = cmul(W[5], W8); W[14] = cmul(W[6], W8);
}

// pair stage: two FFTs (same butterfly index) share one twiddle set
template<bool NOTW>
__device__ __forceinline__ void stage16_pair(const float2* s0, float2* d0,
                                             const float2* s1, float2* d1,
                                             const float2* __restrict__ tw,
                                             int sh, int ls, int t)
{
    int p = t >> ls;
    int q = t & ((1 << ls) - 1);
    int s = 1 << ls;
    int o = q + (p << (ls + 4));
    u64c y[16];
    if (NOTW) {
        bf16_fwd(s0, t, y); store16_raw(d0, o, s, y);
        bf16_fwd(s1, t, y); store16_raw(d1, o, s, y);
    } else {
        float2 W[15];
        build_W(tw, p, sh, W);
        bf16_fwd(s0, t, y); store16_tw(d0, o, s, y, W);
        bf16_fwd(s1, t, y); store16_tw(d1, o, s, y, W);
    }
}

template<bool NOTW>
__device__ __forceinline__ void stage16_one(const float2* s0, float2* d0,
                                            const float2* __restrict__ tw,
                                            int sh, int ls, int t)
{
    int p = t >> ls;
    int q = t & ((1 << ls) - 1);
    int s = 1 << ls;
    int o = q + (p << (ls + 4));
    u64c y[16];
    bf16_fwd(s0, t, y);
    if (NOTW) {
        store16_raw(d0, o, s, y);
    } else {
        float2 W[15];
        build_W(tw, p, sh, W);
        store16_tw(d0, o, s, y, W);
    }
}

// ---------------- generic stage8 (fwd/inv) for the finalize kernel -----------
template<bool INV, bool NOTW>
__device__ __forceinline__ void stage8(const float2* __restrict__ src,
                                       float2* __restrict__ dst,
                                       const float2* __restrict__ tw,
                                       int sh, int ls, int eighth,
                                       int tid, int nt)
{
    const u64c CC2 = cc2_const();
    for (int t = tid; t < eighth; t += nt) {
        int p = t >> ls;
        int q = t & ((1 << ls) - 1);
        u64c x0 = *(const u64c*)&src[SWI(t)];
        u64c x1 = *(const u64c*)&src[SWI(t + eighth)];
        u64c x2 = *(const u64c*)&src[SWI(t + 2 * eighth)];
        u64c x3 = *(const u64c*)&src[SWI(t + 3 * eighth)];
        u64c x4 = *(const u64c*)&src[SWI(t + 4 * eighth)];
        u64c x5 = *(const u64c*)&src[SWI(t + 5 * eighth)];
        u64c x6 = *(const u64c*)&src[SWI(t + 6 * eighth)];
        u64c x7 = *(const u64c*)&src[SWI(t + 7 * eighth)];

        u64c u0 = cadd(x0, x4), u1 = csub(x0, x4);
        u64c u2 = cadd(x2, x6), u3 = csub(x2, x6);
        u64c e0 = cadd(u0, u2), e2 = csub(u0, u2);
        u64c j3 = cmuli(u3);
        u64c e1, e3;
        if (!INV) { e1 = csub(u1, j3); e3 = cadd(u1, j3); }
        else      { e1 = cadd(u1, j3); e3 = csub(u1, j3); }

        u64c v0 = cadd(x1, x5), v1 = csub(x1, x5);
        u64c v2 = cadd(x3, x7), v3 = csub(x3, x7);
        u64c o0 = cadd(v0, v2), o2 = csub(v0, v2);
        u64c k3 = cmuli(v3);
        u64c o1, o3;
        if (!INV) { o1 = csub(v1, k3); o3 = cadd(v1, k3); }
        else      { o1 = cadd(v1, k3); o3 = csub(v1, k3); }

        u64c t1, t2, t3;
        if (!INV) {
            t1 = w8m1(o1, CC2);
            t2 = cmulmi(o2);
            t3 = w8m3(o3, CC2);
        } else {
            t1 = cscale(cadd(o1, cmuli(o1)), CC2);
            t2 = cmuli(o2);
            t3 = cscale(cmuli(cadd(o3, cmuli(o3))), CC2);
        }
        u64c y0 = cadd(e0, o0), y4 = csub(e0, o0);
        u64c y1 = cadd(e1, t1), y5 = csub(e1, t1);
        u64c y2 = cadd(e2, t2), y6 = csub(e2, t2);
        u64c y3 = cadd(e3, t3), y7 = csub(e3, t3);

        int s = 1 << ls;
        int o = q + (p << (ls + 3));
        if (NOTW) {
            *(u64c*)&dst[SWI(o)]       = y0;
            *(u64c*)&dst[SWI(o + s)]   = y1;
            *(u64c*)&dst[SWI(o + 2*s)] = y2;
            *(u64c*)&dst[SWI(o + 3*s)] = y3;
            *(u64c*)&dst[SWI(o + 4*s)] = y4;
            *(u64c*)&dst[SWI(o + 5*s)] = y5;
            *(u64c*)&dst[SWI(o + 6*s)] = y6;
            *(u64c*)&dst[SWI(o + 7*s)] = y7;
        } else {
            float2 w1 = tw[p << sh];
            float2 w2 = tw[(2 * p) << sh];
            float2 w4 = tw[(4 * p) << sh];
            if (INV) { w1.y = -w1.y; w2.y = -w2.y; w4.y = -w4.y; }
            float2 w3 = cmul(w1, w2);
            float2 w5 = cmul(w1, w4);
            float2 w6 = cmul(w2, w4);
            float2 w7 = cmul(w3, w4);
            dst[SWI(o)]       = unpk(y0);
            dst[SWI(o + s)]   = cmul(unpk(y1), w1);
            dst[SWI(o + 2*s)] = cmul(unpk(y2), w2);
            dst[SWI(o + 3*s)] = cmul(unpk(y3), w3);
            dst[SWI(o + 4*s)] = cmul(unpk(y4), w4);
            dst[SWI(o + 5*s)] = cmul(unpk(y5), w5);
            dst[SWI(o + 6*s)] = cmul(unpk(y6), w6);
            dst[SWI(o + 7*s)] = cmul(unpk(y7), w7);
        }
    }
}

template<bool INV>
__device__ void fft4096_r8(float2* A, float2* B, const float2* tw, int tid, int nt)
{
    stage8<INV, false>(A, B, tw, 0, 0, 512, tid, nt); __syncthreads();
    stage8<INV, false>(B, A, tw, 3, 3, 512, tid, nt); __syncthreads();
    stage8<INV, false>(A, B, tw, 6, 6, 512, tid, nt); __syncthreads();
    stage8<INV, true >(B, A, tw, 9, 9, 512, tid, nt); __syncthreads();
}

// Hermitian unpack (2x-scaled): Z = R + i*I with R,I real spectra.
__device__ __forceinline__ void unpack2(float2 Zk, float2 Zm, float2& R, float2& I)
{
    R = make_float2(Zk.x + Zm.x,  Zk.y - Zm.y);
    I = make_float2(Zk.y + Zm.y, -(Zk.x - Zm.x));
}

__global__ void zero_kernel()
{
    int i = blockIdx.x * blockDim.x + threadIdx.x;
    int n = NB * NSPEC * 2;
    if (i < n) {
        ((float*)g_acc2)[i] = 0.f;
        ((float*)g_acc3)[i] = 0.f;
    }
    if (i < NB * CCH) ((float*)g_first)[i] = 0.f;
}

__global__ void __launch_bounds__(NTHR, 1)
poly_sketch_kernel(const float* __restrict__ x,
                   const int* __restrict__ h_idx,
                   const int* __restrict__ s_bits)
{
    extern __shared__ float2 smem[];
    float2* tw = smem;                  // NTW
    float2* A1 = smem + NTW;            // pixel1 Z buffers
    float2* B1 = A1 + APAD;
    float2* A2 = B1 + APAD;             // pixel2 Z buffers
    float2* B2 = A2 + APAD;
    float2* AD = B2 + APAD;             // packed s2(p1) + i*s2(p2)
    float2* BD = AD + APAD;

    int tid  = threadIdx.x;
    int b    = blockIdx.x / SLOTS;
    int slot = blockIdx.x % SLOTS;

    for (int j = tid; j < NTW; j += NTHR) {
        float sn, cs;
        sincospif(-(float)j * (1.0f / 2048.0f), &sn, &cs);
        tw[j] = make_float2(cs, sn);
    }
    for (int j = tid; j < APAD; j += NTHR) {
        A1[j] = make_float2(0.f, 0.f);
        A2[j] = make_float2(0.f, 0.f);
        AD[j] = make_float2(0.f, 0.f);
    }

    int   h0 = h_idx[tid], h1 = h_idx[CCH + tid], h2 = h_idx[2 * CCH + tid];
    float s0 = (float)(2 * s_bits[tid] - 1);
    float s1 = (float)(2 * s_bits[CCH + tid] - 1);
    float s2 = (float)(2 * s_bits[2 * CCH + tid] - 1);
    __syncthreads();

    float2 a2[4], a3[4], m2, m3;
    #pragma unroll
    for (int i = 0; i < 4; i++) { a2[i] = make_float2(0.f, 0.f); a3[i] = make_float2(0.f, 0.f); }
    m2 = make_float2(0.f, 0.f); m3 = make_float2(0.f, 0.f);
    float xsum = 0.f;

    const float* xrow = x + (size_t)b * NPIX * CCH + tid;
    float x1 = xrow[(size_t)slot * CCH];
    float x2 = (slot + SLOTS < NPIX) ? xrow[(size_t)(slot + SLOTS) * CCH] : 0.f;

    float2 *sA1 = A1, *sB1 = B1, *sA2 = A2, *sB2 = B2, *sAD = AD, *sBD = BD;

    for (int pix = slot; pix < NPIX; pix += 2 * SLOTS) {
        atomicAdd(&sA1[SWI(h0)].x, x1 * s0);
        atomicAdd(&sA1[SWI(h1)].y, x1 * s1);
        atomicAdd(&sA2[SWI(h0)].x, x2 * s0);
        atomicAdd(&sA2[SWI(h1)].y, x2 * s1);
        atomicAdd(&sAD[SWI(h2)].x, x1 * s2);
        atomicAdd(&sAD[SWI(h2)].y, x2 * s2);
        xsum += x1 + x2;
        __syncthreads();

        int n1 = pix + 2 * SLOTS, n2 = pix + 3 * SLOTS;
        float xn1 = (n1 < NPIX) ? xrow[(size_t)n1 * CCH] : 0.f;
        float xn2 = (n2 < NPIX) ? xrow[(size_t)n2 * CCH] : 0.f;

        // phase 1 (ls=0, sh=0)
        if (tid < 256) stage16_pair<false>(sA1, sB1, sAD, sBD, tw, 0, 0, tid);
        else           stage16_one<false>(sA2, sB2, tw, 0, 0, tid - 256);
        __syncthreads();
        // phase 2 (ls=4, sh=4)
        if (tid < 256) stage16_pair<false>(sB1, sA1, sBD, sAD, tw, 4, 4, tid);
        else           stage16_one<false>(sB2, sA2, tw, 4, 4, tid - 256);
        __syncthreads();
        // phase 3 (ls=8, no twiddles)
        if (tid < 256) stage16_pair<true>(sA1, sB1, sAD, sBD, tw, 0, 8, tid);
        else           stage16_one<true>(sA2, sB2, tw, 0, 8, tid - 256);
        __syncthreads();
        // spectra: Z1 in sB1, Z2 in sB2, Dspec in sBD

        #pragma unroll
        for (int jj = 0; jj < 2; jj++) {
            int k  = tid + jj * 512;               // 0..1023
            int km = (NFFT - k) & (NFFT - 1);
            int kb = 2048 - k;
            int kc = 2048 + k;
            float2 Z1k = sB1[SWI(k)],  Z1m = sB1[SWI(km)];
            float2 Z1b = sB1[SWI(kb)], Z1c = sB1[SWI(kc)];
            float2 Z2k = sB2[SWI(k)],  Z2m = sB2[SWI(km)];
            float2 Z2b = sB2[SWI(kb)], Z2c = sB2[SWI(kc)];
            float2 Dk  = sBD[SWI(k)],  Dm  = sBD[SWI(km)];
            float2 Db  = sBD[SWI(kb)], Dc  = sBD[SWI(kc)];

            float2 F0, F1, G0, G1, H0, H1;
            unpack2(Z1k, Z1m, F0, F1);
            unpack2(Z2k, Z2m, G0, G1);
            unpack2(Dk,  Dm,  H0, H1);
            float2 P2 = cmul(F0, F1), P3 = cmul(P2, H0);
            float2 Q2 = cmul(G0, G1), Q3 = cmul(Q2, H1);
            a2[2*jj].x += P2.x + Q2.x; a2[2*jj].y += P2.y + Q2.y;
            a3[2*jj].x += P3.x + Q3.x; a3[2*jj].y += P3.y + Q3.y;

            unpack2(Z1b, Z1c, F0, F1);
            unpack2(Z2b, Z2c, G0, G1);
            unpack2(Db,  Dc,  H0, H1);
            P2 = cmul(F0, F1); P3 = cmul(P2, H0);
            Q2 = cmul(G0, G1); Q3 = cmul(Q2, H1);
            a2[2*jj+1].x += P2.x + Q2.x; a2[2*jj+1].y += P2.y + Q2.y;
            a3[2*jj+1].x += P3.x + Q3.x; a3[2*jj+1].y += P3.y + Q3.y;

            float2 z = make_float2(0.f, 0.f);
            sB1[SWI(k)] = z; sB1[SWI(km)] = z; sB1[SWI(kb)] = z; sB1[SWI(kc)] = z;
            sB2[SWI(k)] = z; sB2[SWI(km)] = z; sB2[SWI(kb)] = z; sB2[SWI(kc)] = z;
            sBD[SWI(k)] = z; sBD[SWI(km)] = z; sBD[SWI(kb)] = z; sBD[SWI(kc)] = z;
        }
        if (tid == 0) {                       // self-paired bin 1024
            float2 Z1k = sB1[SWI(1024)], Z1m = sB1[SWI(3072)];
            float2 Z2k = sB2[SWI(1024)], Z2m = sB2[SWI(3072)];
            float2 Dk  = sBD[SWI(1024)], Dm  = sBD[SWI(3072)];
            float2 F0, F1, G0, G1, H0, H1;
            unpack2(Z1k, Z1m, F0, F1);
            unpack2(Z2k, Z2m, G0, G1);
            unpack2(Dk,  Dm,  H0, H1);
            float2 P2 = cmul(F0, F1), P3 = cmul(P2, H0);
            float2 Q2 = cmul(G0, G1), Q3 = cmul(Q2, H1);
            m2.x += P2.x + Q2.x; m2.y += P2.y + Q2.y;
            m3.x += P3.x + Q3.x; m3.y += P3.y + Q3.y;
            float2 z = make_float2(0.f, 0.f);
            sB1[SWI(1024)] = z; sB1[SWI(3072)] = z;
            sB2[SWI(1024)] = z; sB2[SWI(3072)] = z;
            sBD[SWI(1024)] = z; sBD[SWI(3072)] = z;
        }

        float2* t0;
        t0 = sA1; sA1 = sB1; sB1 = t0;
        t0 = sA2; sA2 = sB2; sB2 = t0;
        t0 = sAD; sAD = sBD; sBD = t0;

        x1 = xn1; x2 = xn2;
        __syncthreads();
    }

    int bins[4] = { tid, 2048 - tid, tid + 512, 1536 - tid };
    #pragma unroll
    for (int i = 0; i < 4; i++) {
        atomicAdd(&g_acc2[b][bins[i]].x, a2[i].x);
        atomicAdd(&g_acc2[b][bins[i]].y, a2[i].y);
        atomicAdd(&g_acc3[b][bins[i]].x, a3[i].x);
        atomicAdd(&g_acc3[b][bins[i]].y, a3[i].y);
    }
    if (tid == 0) {
        atomicAdd(&g_acc2[b][1024].x, m2.x);
        atomicAdd(&g_acc2[b][1024].y, m2.y);
        atomicAdd(&g_acc3[b][1024].x, m3.x);
        atomicAdd(&g_acc3[b][1024].y, m3.y);
    }
    atomicAdd(&g_first[b][tid], xsum);
}

__global__ void __launch_bounds__(NTHF, 1)
finalize_kernel(const float* __restrict__ alpha, float* __restrict__ out)
{
    extern __shared__ float2 smem[];
    float2* tw  = smem;                 // NTW
    float2* A   = smem + NTW;
    float2* B   = A + APAD;
    float*  phi = (float*)(B + APAD);   // 8712 floats
    __shared__ float red[17];

    int tid = threadIdx.x;
    int b   = blockIdx.x;

    for (int j = tid; j < NTW; j += NTHF) {
        float sn, cs;
        sincospif(-(float)j * (1.0f / 2048.0f), &sn, &cs);
        tw[j] = make_float2(cs, sn);
    }
    __syncthreads();

    // accumulators carry 4x (acc2) and 8x (acc3) -> fold 0.25 / 0.125 here
    const float inv_n = 1.0f / ((float)NPIX * (float)NFFT);

    for (int i = tid; i < NFFT; i += NTHF) {
        if (i <= NHALF) A[SWI(i)] = g_acc2[b][i];
        else { float2 v = g_acc2[b][NFFT - i]; A[SWI(i)] = make_float2(v.x, -v.y); }
    }
    __syncthreads();
    fft4096_r8<true>(A, B, tw, tid, NTHF);
    {
        float a2c = alpha[2] * inv_n * 0.25f;
        for (int i = tid; i < NFFT; i += NTHF) phi[513 + i] = A[SWI(i)].x * a2c;
    }
    __syncthreads();

    for (int i = tid; i < NFFT; i += NTHF) {
        if (i <= NHALF) A[SWI(i)] = g_acc3[b][i];
        else { float2 v = g_acc3[b][NFFT - i]; A[SWI(i)] = make_float2(v.x, -v.y); }
    }
    __syncthreads();
    fft4096_r8<true>(A, B, tw, tid, NTHF);
    {
        float a3c = alpha[3] * inv_n * 0.125f;
        for (int i = tid; i < NFFT; i += NTHF) phi[513 + NFFT + i] = A[SWI(i)].x * a3c;
    }

    if (tid == 0) phi[0] = alpha[0];
    phi[1 + tid] = alpha[1] * g_first[b][tid] * (1.0f / (float)NPIX);
    __syncthreads();

    float lsum = 0.f;
    for (int i = tid; i < DOUT; i += NTHF) {
        float v = phi[i];
        float r;
        if (v > 0.f)      r =  sqrtf(v + 1e-12f);
        else if (v < 0.f) r = -sqrtf(-v + 1e-12f);
        else              r = 0.f;
        phi[i] = r;
        lsum += r * r;
    }
    #pragma unroll
    for (int off = 16; off > 0; off >>= 1)
        lsum += __shfl_down_sync(0xffffffffu, lsum, off);
    if ((tid & 31) == 0) red[tid >> 5] = lsum;
    __syncthreads();
    if (tid == 0) {
        float s = 0.f;
        #pragma unroll
        for (int k = 0; k < 16; k++) s += red[k];
        red[16] = 1.0f / sqrtf(s);
    }
    __syncthreads();
    float rn = red[16];
    for (int i = tid; i < DOUT; i += NTHF)
        out[(size_t)b * DOUT + i] = phi[i] * rn;
}

extern "C" void kernel_launch(void* const* d_in, const int* in_sizes, int n_in,
                              void* d_out, int out_size)
{
    const float* x     = (const float*)d_in[0];
    const float* alpha = (const float*)d_in[1];
    const int*   h     = (const int*)d_in[2];
    const int*   sb    = (const int*)d_in[3];
    float*       out   = (float*)d_out;

    const int MAIN_SMEM = (NTW + 6 * APAD) * (int)sizeof(float2);            // 219136
    const int FIN_SMEM  = (NTW + 2 * APAD) * (int)sizeof(float2) + 8712 * 4; // 118816

    cudaFuncSetAttribute(poly_sketch_kernel,
                         cudaFuncAttributeMaxDynamicSharedMemorySize, MAIN_SMEM);
    cudaFuncSetAttribute(finalize_kernel,
                         cudaFuncAttributeMaxDynamicSharedMemorySize, FIN_SMEM);

    zero_kernel<<<(NB * NSPEC * 2 + 255) / 256, 256>>>();
    poly_sketch_kernel<<<NB * SLOTS, NTHR, MAIN_SMEM>>>(x, h, sb);
    finalize_kernel<<<NB, NTHF, FIN_SMEM>>>(alpha, out);
}